// round 1
// baseline (speedup 1.0000x reference)
#include <cuda_runtime.h>
#include <cstdint>

#define N_NODES 50000
#define N_EDGES 25000
#define NNZ     800000
#define DIM     256

// ---------------- scratch (device globals; no allocation allowed) -----------
__device__ float g_Z [N_NODES * DIM];     // d_v * (X@W + b)      (51.2 MB)
__device__ float g_S2[N_EDGES * DIM];     // d_e * (H^T Z)        (25.6 MB)
__device__ int   g_deg_v[N_NODES];
__device__ int   g_deg_e[N_EDGES];
__device__ float g_dv[N_NODES];
__device__ float g_de[N_EDGES];
__device__ int   g_off_e[N_EDGES + 1];
__device__ int   g_off_n[N_NODES + 1];
__device__ int   g_cur_e[N_EDGES];
__device__ int   g_cur_n[N_NODES];
__device__ int   g_adj_e[NNZ];            // node ids grouped by edge
__device__ int   g_adj_n[NNZ];            // edge ids grouped by node
__device__ int   g_is64;                  // 1 if indices are int64, 0 if int32

// ---------------- small helpers ---------------------------------------------
__device__ __forceinline__ int idx_at(const void* p, int i, int is64) {
    if (is64) return (int)(((const long long*)p)[i]);
    return ((const int*)p)[i];
}
__device__ __forceinline__ float4 f4add(float4 a, float4 b) {
    a.x += b.x; a.y += b.y; a.z += b.z; a.w += b.w; return a;
}
__device__ __forceinline__ float4 f4scale(float4 a, float s) {
    a.x *= s; a.y *= s; a.z *= s; a.w *= s; return a;
}

// ---------------- 0. detect index dtype -------------------------------------
__global__ void detect_kernel(const void* node_idx) {
    // int64 indices: every qword < 2^32 (values < 50000).
    // int32 indices: qword = lo | hi<<32 with hi a random value in [0,50000):
    // P(64 consecutive hi words all zero) ~ 0.
    const unsigned long long* q = (const unsigned long long*)node_idx;
    int is64 = 1;
    for (int i = 0; i < 64; i++) {
        if (q[i] >= (1ull << 32)) { is64 = 0; break; }
    }
    g_is64 = is64;
}

// ---------------- 1. zero counters ------------------------------------------
__global__ void zero_kernel() {
    int i = blockIdx.x * blockDim.x + threadIdx.x;
    if (i < N_NODES) { g_deg_v[i] = 0; g_cur_n[i] = 0; }
    if (i < N_EDGES) { g_deg_e[i] = 0; g_cur_e[i] = 0; }
}

// ---------------- 2. degree histogram ---------------------------------------
__global__ void count_kernel(const void* ni, const void* ei) {
    int i = blockIdx.x * blockDim.x + threadIdx.x;
    if (i >= NNZ) return;
    int is64 = g_is64;
    int n = idx_at(ni, i, is64);
    int e = idx_at(ei, i, is64);
    atomicAdd(&g_deg_v[n], 1);
    atomicAdd(&g_deg_e[e], 1);
}

// ---------------- 3. single-block exclusive scan + D^-1 / D^-1/2 ------------
// mode 0: dinv = 1/deg ; mode 1: dinv = deg^-0.5
__global__ void scan_kernel(const int* __restrict__ deg, int n,
                            int* __restrict__ off, float* __restrict__ dinv,
                            int mode) {
    __shared__ int tmp[1024];
    __shared__ int carry;
    int tid = threadIdx.x;
    if (tid == 0) carry = 0;
    __syncthreads();
    for (int base = 0; base < n; base += 1024) {
        int i = base + tid;
        int v = (i < n) ? deg[i] : 0;
        tmp[tid] = v;
        __syncthreads();
        #pragma unroll
        for (int s = 1; s < 1024; s <<= 1) {
            int t = (tid >= s) ? tmp[tid - s] : 0;
            __syncthreads();
            tmp[tid] += t;
            __syncthreads();
        }
        int c = carry;
        if (i < n) {
            off[i]  = c + tmp[tid] - v;               // exclusive
            dinv[i] = (v > 0)
                      ? (mode ? rsqrtf((float)v) : 1.0f / (float)v)
                      : 0.0f;
        }
        __syncthreads();
        if (tid == 0) carry = c + tmp[1023];
        __syncthreads();
    }
    if (tid == 0) off[n] = carry;
}

// ---------------- 4. CSR fill (counting-sort scatter of indices) ------------
__global__ void fill_kernel(const void* ni, const void* ei) {
    int i = blockIdx.x * blockDim.x + threadIdx.x;
    if (i >= NNZ) return;
    int is64 = g_is64;
    int n = idx_at(ni, i, is64);
    int e = idx_at(ei, i, is64);
    int pe = atomicAdd(&g_cur_e[e], 1);
    g_adj_e[g_off_e[e] + pe] = n;
    int pn = atomicAdd(&g_cur_n[n], 1);
    g_adj_n[g_off_n[n] + pn] = e;
}

// ---------------- 5. GEMM: Z = diag(d_v) * (X @ W + b) ----------------------
// BM=128, BN=64, BK=8, 256 threads (16x16), each thread 8x4 outputs.
__global__ void gemm_kernel(const float* __restrict__ X,
                            const float* __restrict__ W,
                            const float* __restrict__ bias) {
    __shared__ __align__(16) float As[8][132];   // [k][m], padded
    __shared__ __align__(16) float Bs[8][64];    // [k][n]

    int t  = threadIdx.x;
    int tx = t & 15;      // col group (4 cols)
    int ty = t >> 4;      // row group (rows ty*4..+3 and 64+ty*4..+3)
    int m0 = blockIdx.x * 128;
    int n0 = blockIdx.y * 64;

    float acc[8][4];
    #pragma unroll
    for (int i = 0; i < 8; i++)
        #pragma unroll
        for (int j = 0; j < 4; j++) acc[i][j] = 0.0f;

    int lrow = t >> 1;     // 0..127
    int lkq  = t & 1;      // which float4 along k

    for (int k0 = 0; k0 < DIM; k0 += 8) {
        // A tile: 128 rows x 8 k  (transposed store into As[k][m])
        float4 av = make_float4(0.f, 0.f, 0.f, 0.f);
        int gr = m0 + lrow;
        if (gr < N_NODES)
            av = *(const float4*)&X[(size_t)gr * DIM + k0 + lkq * 4];
        As[lkq * 4 + 0][lrow] = av.x;
        As[lkq * 4 + 1][lrow] = av.y;
        As[lkq * 4 + 2][lrow] = av.z;
        As[lkq * 4 + 3][lrow] = av.w;
        // B tile: 8 k x 64 n
        if (t < 128) {
            int bkr = t >> 4, bnq = t & 15;
            float4 bv = *(const float4*)&W[(size_t)(k0 + bkr) * DIM + n0 + bnq * 4];
            *(float4*)&Bs[bkr][bnq * 4] = bv;
        }
        __syncthreads();
        #pragma unroll
        for (int k = 0; k < 8; k++) {
            float4 a0 = *(const float4*)&As[k][ty * 4];
            float4 a1 = *(const float4*)&As[k][64 + ty * 4];
            float4 b  = *(const float4*)&Bs[k][tx * 4];
            float ar[8] = {a0.x, a0.y, a0.z, a0.w, a1.x, a1.y, a1.z, a1.w};
            float br[4] = {b.x, b.y, b.z, b.w};
            #pragma unroll
            for (int i = 0; i < 8; i++)
                #pragma unroll
                for (int j = 0; j < 4; j++)
                    acc[i][j] += ar[i] * br[j];
        }
        __syncthreads();
    }

    // epilogue: Z[r][c] = d_v[r] * (acc + b[c])
    float4 bb = *(const float4*)&bias[n0 + tx * 4];
    float brow[4] = {bb.x, bb.y, bb.z, bb.w};
    #pragma unroll
    for (int i = 0; i < 8; i++) {
        int r = m0 + ((i < 4) ? (ty * 4 + i) : (64 + ty * 4 + (i - 4)));
        if (r < N_NODES) {
            float dv = g_dv[r];
            float4 out;
            out.x = dv * (acc[i][0] + brow[0]);
            out.y = dv * (acc[i][1] + brow[1]);
            out.z = dv * (acc[i][2] + brow[2]);
            out.w = dv * (acc[i][3] + brow[3]);
            *(float4*)&g_Z[(size_t)r * DIM + n0 + tx * 4] = out;
        }
    }
}

// ---------------- 6. phase 1: S2[e] = d_e[e] * sum_{n in e} Z[n] ------------
// one warp per hyperedge; lane holds cols [4l..4l+3] and [128+4l..128+4l+3]
__global__ void edge_gather_kernel() {
    int w    = (blockIdx.x * blockDim.x + threadIdx.x) >> 5;
    int lane = threadIdx.x & 31;
    if (w >= N_EDGES) return;
    int s = g_off_e[w], e = g_off_e[w + 1];
    float4 a0 = make_float4(0.f, 0.f, 0.f, 0.f);
    float4 a1 = make_float4(0.f, 0.f, 0.f, 0.f);
    int j = s;
    for (; j + 2 <= e; j += 2) {
        int n0 = g_adj_e[j], n1 = g_adj_e[j + 1];
        const float4* p0 = (const float4*)(g_Z + (size_t)n0 * DIM);
        const float4* p1 = (const float4*)(g_Z + (size_t)n1 * DIM);
        float4 v00 = p0[lane], v01 = p0[lane + 32];
        float4 v10 = p1[lane], v11 = p1[lane + 32];
        a0 = f4add(a0, v00); a1 = f4add(a1, v01);
        a0 = f4add(a0, v10); a1 = f4add(a1, v11);
    }
    if (j < e) {
        int n0 = g_adj_e[j];
        const float4* p0 = (const float4*)(g_Z + (size_t)n0 * DIM);
        a0 = f4add(a0, p0[lane]);
        a1 = f4add(a1, p0[lane + 32]);
    }
    float de = g_de[w];
    float4* out = (float4*)(g_S2 + (size_t)w * DIM);
    out[lane]      = f4scale(a0, de);
    out[lane + 32] = f4scale(a1, de);
}

// ---------------- 7. phase 2: out[n] = d_v[n] * sum_{e of n} S2[e] ----------
__global__ void node_gather_kernel(float* __restrict__ out_g) {
    int w    = (blockIdx.x * blockDim.x + threadIdx.x) >> 5;
    int lane = threadIdx.x & 31;
    if (w >= N_NODES) return;
    int s = g_off_n[w], e = g_off_n[w + 1];
    float4 a0 = make_float4(0.f, 0.f, 0.f, 0.f);
    float4 a1 = make_float4(0.f, 0.f, 0.f, 0.f);
    int j = s;
    for (; j + 2 <= e; j += 2) {
        int e0 = g_adj_n[j], e1 = g_adj_n[j + 1];
        const float4* p0 = (const float4*)(g_S2 + (size_t)e0 * DIM);
        const float4* p1 = (const float4*)(g_S2 + (size_t)e1 * DIM);
        float4 v00 = p0[lane], v01 = p0[lane + 32];
        float4 v10 = p1[lane], v11 = p1[lane + 32];
        a0 = f4add(a0, v00); a1 = f4add(a1, v01);
        a0 = f4add(a0, v10); a1 = f4add(a1, v11);
    }
    if (j < e) {
        int e0 = g_adj_n[j];
        const float4* p0 = (const float4*)(g_S2 + (size_t)e0 * DIM);
        a0 = f4add(a0, p0[lane]);
        a1 = f4add(a1, p0[lane + 32]);
    }
    float dv = g_dv[w];
    float4* out = (float4*)(out_g + (size_t)w * DIM);
    out[lane]      = f4scale(a0, dv);
    out[lane + 32] = f4scale(a1, dv);
}

// ---------------- launch -----------------------------------------------------
extern "C" void kernel_launch(void* const* d_in, const int* in_sizes, int n_in,
                              void* d_out, int out_size) {
    const float* X  = (const float*)d_in[0];
    const void*  ni = d_in[1];
    const void*  ei = d_in[2];
    const float* W  = (const float*)d_in[3];
    const float* b  = (const float*)d_in[4];
    float* out = (float*)d_out;

    int* deg_e_p; int* off_e_p; float* de_p;
    int* deg_v_p; int* off_n_p; float* dv_p;
    cudaGetSymbolAddress((void**)&deg_e_p, g_deg_e);
    cudaGetSymbolAddress((void**)&off_e_p, g_off_e);
    cudaGetSymbolAddress((void**)&de_p,    g_de);
    cudaGetSymbolAddress((void**)&deg_v_p, g_deg_v);
    cudaGetSymbolAddress((void**)&off_n_p, g_off_n);
    cudaGetSymbolAddress((void**)&dv_p,    g_dv);

    detect_kernel<<<1, 1>>>(ni);
    zero_kernel<<<(N_NODES + 255) / 256, 256>>>();
    count_kernel<<<(NNZ + 255) / 256, 256>>>(ni, ei);
    scan_kernel<<<1, 1024>>>(deg_e_p, N_EDGES, off_e_p, de_p, 0);
    scan_kernel<<<1, 1024>>>(deg_v_p, N_NODES, off_n_p, dv_p, 1);
    fill_kernel<<<(NNZ + 255) / 256, 256>>>(ni, ei);

    dim3 ggrid((N_NODES + 127) / 128, DIM / 64);
    gemm_kernel<<<ggrid, 256>>>(X, W, b);

    edge_gather_kernel<<<(N_EDGES * 32 + 255) / 256, 256>>>();
    node_gather_kernel<<<(N_NODES * 32 + 255) / 256, 256>>>(out);
}

// round 2
// speedup vs baseline: 1.2928x; 1.2928x over previous
#include <cuda_runtime.h>
#include <cstdint>

#define N_NODES 50000
#define N_EDGES 25000
#define NNZ     800000
#define DIM     256

#define CH_E ((N_EDGES + 1023) / 1024)   // 25 chunks
#define CH_N ((N_NODES + 1023) / 1024)   // 49 chunks

// ---------------- scratch (device globals; no allocation allowed) -----------
__device__ __align__(16) float g_Z [N_NODES * DIM];   // X@W + b       (51.2 MB)
__device__ __align__(16) float g_S2[N_EDGES * DIM];   // d_e * (H^T D_v Y) (25.6 MB)
__device__ int   g_deg_v[N_NODES];
__device__ int   g_deg_e[N_EDGES];
__device__ float g_dv[N_NODES];
__device__ float g_de[N_EDGES];
__device__ int   g_off_e[N_EDGES + 1];
__device__ int   g_off_n[N_NODES + 1];
__device__ int   g_cur_e[N_EDGES];
__device__ int   g_cur_n[N_NODES];
__device__ int   g_adj_e[NNZ];            // node ids grouped by edge
__device__ int   g_adj_n[NNZ];            // edge ids grouped by node
__device__ int   g_part_e[32];            // block partial sums (edges)
__device__ int   g_part_n[64];            // block partial sums (nodes)
__device__ int   g_is64;                  // 1 if indices are int64

// ---------------- small helpers ---------------------------------------------
__device__ __forceinline__ int idx_at(const void* p, int i, int is64) {
    if (is64) return (int)(((const long long*)p)[i]);
    return ((const int*)p)[i];
}
__device__ __forceinline__ float4 f4add(float4 a, float4 b) {
    a.x += b.x; a.y += b.y; a.z += b.z; a.w += b.w; return a;
}
__device__ __forceinline__ float4 f4fma(float4 a, float4 v, float s) {
    a.x = fmaf(v.x, s, a.x); a.y = fmaf(v.y, s, a.y);
    a.z = fmaf(v.z, s, a.z); a.w = fmaf(v.w, s, a.w); return a;
}
__device__ __forceinline__ float4 f4scale(float4 a, float s) {
    a.x *= s; a.y *= s; a.z *= s; a.w *= s; return a;
}

// ---------------- launch #1: detect index dtype ------------------------------
__global__ void detect_kernel(const void* node_idx) {
    const unsigned long long* q = (const unsigned long long*)node_idx;
    int is64 = 1;
    #pragma unroll 8
    for (int i = 0; i < 64; i++)
        if (q[i] >= (1ull << 32)) is64 = 0;
    g_is64 = is64;
}

// ---------------- launch #2: zero counters -----------------------------------
__global__ void zero_kernel() {
    int i = blockIdx.x * blockDim.x + threadIdx.x;
    if (i < N_NODES) { g_deg_v[i] = 0; g_cur_n[i] = 0; }
    if (i < N_EDGES) { g_deg_e[i] = 0; g_cur_e[i] = 0; }
}

// ---------------- launch #3: degree histogram --------------------------------
__global__ void count_kernel(const void* ni, const void* ei) {
    int i = blockIdx.x * blockDim.x + threadIdx.x;
    if (i >= NNZ) return;
    int is64 = g_is64;
    atomicAdd(&g_deg_v[idx_at(ni, i, is64)], 1);
    atomicAdd(&g_deg_e[idx_at(ei, i, is64)], 1);
}

// ---------------- launch #4: scan phase 1 (block-local scan + partials) ------
// blockIdx.y: 0 = edges, 1 = nodes. Also computes d_e = 1/deg, d_v = deg^-0.5.
__global__ void scan_p1_kernel() {
    int which = blockIdx.y;
    int n        = which ? N_NODES : N_EDGES;
    const int* deg = which ? g_deg_v : g_deg_e;
    int*  off    = which ? g_off_n : g_off_e;
    float* dinv  = which ? g_dv    : g_de;
    int*  part   = which ? g_part_n : g_part_e;

    int base = blockIdx.x * 1024;
    if (base >= n) return;
    int tid = threadIdx.x;
    int i = base + tid;
    int v = (i < n) ? deg[i] : 0;

    // warp inclusive scan
    int x = v;
    int lane = tid & 31, warp = tid >> 5;
    #pragma unroll
    for (int s = 1; s < 32; s <<= 1) {
        int t = __shfl_up_sync(0xffffffffu, x, s);
        if (lane >= s) x += t;
    }
    __shared__ int wsum[32];
    if (lane == 31) wsum[warp] = x;
    __syncthreads();
    if (warp == 0) {
        int y = wsum[lane];
        #pragma unroll
        for (int s = 1; s < 32; s <<= 1) {
            int t = __shfl_up_sync(0xffffffffu, y, s);
            if (lane >= s) y += t;
        }
        wsum[lane] = y;
    }
    __syncthreads();
    int incl = x + (warp ? wsum[warp - 1] : 0);
    if (i < n) {
        off[i] = incl - v;                 // block-local exclusive scan
        dinv[i] = (v > 0)
                  ? (which ? rsqrtf((float)v) : 1.0f / (float)v)
                  : 0.0f;
    }
    if (tid == 1023) part[blockIdx.x] = incl;   // block total
}

// ---------------- launch #5: GEMM  Z = X @ W + b  (profiled slot) ------------
// 128x128 tile, BK=8, 256 threads, 8x8 per thread.
__global__ __launch_bounds__(256, 2)
void gemm_kernel(const float* __restrict__ X,
                 const float* __restrict__ W,
                 const float* __restrict__ bias) {
    __shared__ __align__(16) float As[8][132];   // [k][m]
    __shared__ __align__(16) float Bs[8][128];   // [k][n]

    int t  = threadIdx.x;
    int tx = t & 15;       // col quad
    int ty = t >> 4;       // row quad
    int m0 = blockIdx.x * 128;
    int n0 = blockIdx.y * 128;

    float acc[8][8];
    #pragma unroll
    for (int i = 0; i < 8; i++)
        #pragma unroll
        for (int j = 0; j < 8; j++) acc[i][j] = 0.0f;

    int lrow = t >> 1;     // 0..127  (A loader)
    int lkq  = t & 1;
    int bkr  = t >> 5;     // 0..7    (B loader)
    int bnq  = t & 31;

    for (int k0 = 0; k0 < DIM; k0 += 8) {
        float4 av = make_float4(0.f, 0.f, 0.f, 0.f);
        int gr = m0 + lrow;
        if (gr < N_NODES)
            av = *(const float4*)&X[(size_t)gr * DIM + k0 + lkq * 4];
        As[lkq * 4 + 0][lrow] = av.x;
        As[lkq * 4 + 1][lrow] = av.y;
        As[lkq * 4 + 2][lrow] = av.z;
        As[lkq * 4 + 3][lrow] = av.w;

        float4 bv = *(const float4*)&W[(size_t)(k0 + bkr) * DIM + n0 + bnq * 4];
        *(float4*)&Bs[bkr][bnq * 4] = bv;
        __syncthreads();

        #pragma unroll
        for (int k = 0; k < 8; k++) {
            float4 a0 = *(const float4*)&As[k][ty * 4];
            float4 a1 = *(const float4*)&As[k][64 + ty * 4];
            float4 b0 = *(const float4*)&Bs[k][tx * 4];
            float4 b1 = *(const float4*)&Bs[k][64 + tx * 4];
            float ar[8] = {a0.x, a0.y, a0.z, a0.w, a1.x, a1.y, a1.z, a1.w};
            float br[8] = {b0.x, b0.y, b0.z, b0.w, b1.x, b1.y, b1.z, b1.w};
            #pragma unroll
            for (int i = 0; i < 8; i++)
                #pragma unroll
                for (int j = 0; j < 8; j++)
                    acc[i][j] = fmaf(ar[i], br[j], acc[i][j]);
        }
        __syncthreads();
    }

    float4 bb0 = *(const float4*)&bias[n0 + tx * 4];
    float4 bb1 = *(const float4*)&bias[n0 + 64 + tx * 4];
    float brow[8] = {bb0.x, bb0.y, bb0.z, bb0.w, bb1.x, bb1.y, bb1.z, bb1.w};
    #pragma unroll
    for (int i = 0; i < 8; i++) {
        int r = m0 + ((i < 4) ? (ty * 4 + i) : (64 + ty * 4 + (i - 4)));
        if (r < N_NODES) {
            #pragma unroll
            for (int jq = 0; jq < 2; jq++) {
                float4 o;
                o.x = acc[i][jq * 4 + 0] + brow[jq * 4 + 0];
                o.y = acc[i][jq * 4 + 1] + brow[jq * 4 + 1];
                o.z = acc[i][jq * 4 + 2] + brow[jq * 4 + 2];
                o.w = acc[i][jq * 4 + 3] + brow[jq * 4 + 3];
                *(float4*)&g_Z[(size_t)r * DIM + n0 + jq * 64 + tx * 4] = o;
            }
        }
    }
}

// ---------------- launch #6: scan phase 2 (scan the partials) ----------------
__global__ void scan_p2_kernel() {
    __shared__ int pe[32], pn[64];
    int t = threadIdx.x;
    if (t < 32) pe[t] = (t < CH_E) ? g_part_e[t] : 0;
    if (t < 64) pn[t] = (t < CH_N) ? g_part_n[t] : 0;
    __syncthreads();
    #pragma unroll
    for (int s = 1; s < 64; s <<= 1) {
        int ve = (t < 32 && t >= s) ? pe[t - s] : 0;
        int vn = (t < 64 && t >= s) ? pn[t - s] : 0;
        __syncthreads();
        if (t < 32) pe[t] += ve;
        if (t < 64) pn[t] += vn;
        __syncthreads();
    }
    if (t < 32) g_part_e[t] = t ? pe[t - 1] : 0;     // exclusive
    if (t < 64) g_part_n[t] = t ? pn[t - 1] : 0;
    if (t == 0) { g_off_e[N_EDGES] = NNZ; g_off_n[N_NODES] = NNZ; }
}

// ---------------- launch #7: scan phase 3 (add block offsets) ----------------
__global__ void scan_p3_kernel() {
    int which = blockIdx.y;
    int n   = which ? N_NODES : N_EDGES;
    int* off = which ? g_off_n : g_off_e;
    int i = blockIdx.x * 1024 + threadIdx.x;
    if (i < n) off[i] += (which ? g_part_n : g_part_e)[blockIdx.x];
}

// ---------------- launch #8: CSR fill ----------------------------------------
__global__ void fill_kernel(const void* ni, const void* ei) {
    int i = blockIdx.x * blockDim.x + threadIdx.x;
    if (i >= NNZ) return;
    int is64 = g_is64;
    int n = idx_at(ni, i, is64);
    int e = idx_at(ei, i, is64);
    int pe = atomicAdd(&g_cur_e[e], 1);
    g_adj_e[g_off_e[e] + pe] = n;
    int pn = atomicAdd(&g_cur_n[n], 1);
    g_adj_n[g_off_n[n] + pn] = e;
}

// ---------------- launch #9: S2[e] = d_e[e] * sum_{n in e} d_v[n]*Z[n] -------
__global__ void edge_gather_kernel() {
    int w    = (blockIdx.x * blockDim.x + threadIdx.x) >> 5;
    int lane = threadIdx.x & 31;
    if (w >= N_EDGES) return;
    int s = g_off_e[w], e = g_off_e[w + 1];
    float4 a0 = make_float4(0.f, 0.f, 0.f, 0.f);
    float4 a1 = make_float4(0.f, 0.f, 0.f, 0.f);
    int j = s;
    for (; j + 2 <= e; j += 2) {
        int n0 = g_adj_e[j], n1 = g_adj_e[j + 1];
        float dv0 = g_dv[n0], dv1 = g_dv[n1];
        const float4* p0 = (const float4*)(g_Z + (size_t)n0 * DIM);
        const float4* p1 = (const float4*)(g_Z + (size_t)n1 * DIM);
        float4 v00 = p0[lane], v01 = p0[lane + 32];
        float4 v10 = p1[lane], v11 = p1[lane + 32];
        a0 = f4fma(a0, v00, dv0); a1 = f4fma(a1, v01, dv0);
        a0 = f4fma(a0, v10, dv1); a1 = f4fma(a1, v11, dv1);
    }
    if (j < e) {
        int n0 = g_adj_e[j];
        float dv0 = g_dv[n0];
        const float4* p0 = (const float4*)(g_Z + (size_t)n0 * DIM);
        a0 = f4fma(a0, p0[lane], dv0);
        a1 = f4fma(a1, p0[lane + 32], dv0);
    }
    float de = g_de[w];
    float4* out = (float4*)(g_S2 + (size_t)w * DIM);
    out[lane]      = f4scale(a0, de);
    out[lane + 32] = f4scale(a1, de);
}

// ---------------- launch #10: out[n] = d_v[n] * sum_{e of n} S2[e] -----------
__global__ void node_gather_kernel(float* __restrict__ out_g) {
    int w    = (blockIdx.x * blockDim.x + threadIdx.x) >> 5;
    int lane = threadIdx.x & 31;
    if (w >= N_NODES) return;
    int s = g_off_n[w], e = g_off_n[w + 1];
    float4 a0 = make_float4(0.f, 0.f, 0.f, 0.f);
    float4 a1 = make_float4(0.f, 0.f, 0.f, 0.f);
    int j = s;
    for (; j + 2 <= e; j += 2) {
        int e0 = g_adj_n[j], e1 = g_adj_n[j + 1];
        const float4* p0 = (const float4*)(g_S2 + (size_t)e0 * DIM);
        const float4* p1 = (const float4*)(g_S2 + (size_t)e1 * DIM);
        float4 v00 = p0[lane], v01 = p0[lane + 32];
        float4 v10 = p1[lane], v11 = p1[lane + 32];
        a0 = f4add(a0, v00); a1 = f4add(a1, v01);
        a0 = f4add(a0, v10); a1 = f4add(a1, v11);
    }
    if (j < e) {
        int e0 = g_adj_n[j];
        const float4* p0 = (const float4*)(g_S2 + (size_t)e0 * DIM);
        a0 = f4add(a0, p0[lane]);
        a1 = f4add(a1, p0[lane + 32]);
    }
    float dv = g_dv[w];
    float4* out = (float4*)(out_g + (size_t)w * DIM);
    out[lane]      = f4scale(a0, dv);
    out[lane + 32] = f4scale(a1, dv);
}

// ---------------- launch ------------------------------------------------------
extern "C" void kernel_launch(void* const* d_in, const int* in_sizes, int n_in,
                              void* d_out, int out_size) {
    const float* X  = (const float*)d_in[0];
    const void*  ni = d_in[1];
    const void*  ei = d_in[2];
    const float* W  = (const float*)d_in[3];
    const float* b  = (const float*)d_in[4];
    float* out = (float*)d_out;

    detect_kernel<<<1, 1>>>(ni);                                     // 1
    zero_kernel<<<(N_NODES + 255) / 256, 256>>>();                   // 2
    count_kernel<<<(NNZ + 255) / 256, 256>>>(ni, ei);                // 3
    scan_p1_kernel<<<dim3(CH_N, 2), 1024>>>();                       // 4

    dim3 ggrid((N_NODES + 127) / 128, DIM / 128);
    gemm_kernel<<<ggrid, 256>>>(X, W, b);                            // 5 (profiled)

    scan_p2_kernel<<<1, 128>>>();                                    // 6
    scan_p3_kernel<<<dim3(CH_N, 2), 1024>>>();                       // 7
    fill_kernel<<<(NNZ + 255) / 256, 256>>>(ni, ei);                 // 8
    edge_gather_kernel<<<(N_EDGES * 32 + 255) / 256, 256>>>();       // 9
    node_gather_kernel<<<(N_NODES * 32 + 255) / 256, 256>>>(out);    // 10
}

// round 4
// speedup vs baseline: 1.5667x; 1.2119x over previous
#include <cuda_runtime.h>
#include <cuda_bf16.h>
#include <cstdint>

#define N_NODES 50000
#define N_PAD   50048              // 391 * 128
#define N_EDGES 25000
#define NNZ     800000
#define DIM     256

#define CH_E ((N_EDGES + 1023) / 1024)   // 25
#define CH_N ((N_NODES + 1023) / 1024)   // 49

// ---------------- scratch ----------------------------------------------------
__device__ __align__(16) float g_Z [N_NODES * DIM];     // X@W + b
__device__ __align__(16) float g_S2[N_EDGES * DIM];
__device__ __align__(16) __nv_bfloat16 g_Xhi[(size_t)N_PAD * DIM];
__device__ __align__(16) __nv_bfloat16 g_Xlo[(size_t)N_PAD * DIM];
__device__ __align__(16) __nv_bfloat16 g_Wthi[DIM * DIM];  // [n][k]
__device__ __align__(16) __nv_bfloat16 g_Wtlo[DIM * DIM];  // [n][k]
__device__ int   g_deg_v[N_NODES];
__device__ int   g_deg_e[N_EDGES];
__device__ float g_dv[N_NODES];
__device__ float g_de[N_EDGES];
__device__ int   g_off_e[N_EDGES + 1];
__device__ int   g_off_n[N_NODES + 1];
__device__ int   g_cur_e[N_EDGES];
__device__ int   g_cur_n[N_NODES];
__device__ int   g_adj_e[NNZ];
__device__ int   g_adj_n[NNZ];
__device__ int   g_part_e[32];
__device__ int   g_part_n[64];
__device__ int   g_is64;

// ---------------- helpers ----------------------------------------------------
__device__ __forceinline__ int idx_at(const void* p, int i, int is64) {
    if (is64) return (int)(((const long long*)p)[i]);
    return ((const int*)p)[i];
}
__device__ __forceinline__ float4 f4add(float4 a, float4 b) {
    a.x += b.x; a.y += b.y; a.z += b.z; a.w += b.w; return a;
}
__device__ __forceinline__ float4 f4fma(float4 a, float4 v, float s) {
    a.x = fmaf(v.x, s, a.x); a.y = fmaf(v.y, s, a.y);
    a.z = fmaf(v.z, s, a.z); a.w = fmaf(v.w, s, a.w); return a;
}
__device__ __forceinline__ float4 f4scale(float4 a, float s) {
    a.x *= s; a.y *= s; a.z *= s; a.w *= s; return a;
}
__device__ __forceinline__ void mma16816(float* c, const uint32_t* a, const uint32_t* b) {
    asm volatile(
        "mma.sync.aligned.m16n8k16.row.col.f32.bf16.bf16.f32 "
        "{%0,%1,%2,%3}, {%4,%5,%6,%7}, {%8,%9}, {%0,%1,%2,%3};\n"
        : "+f"(c[0]), "+f"(c[1]), "+f"(c[2]), "+f"(c[3])
        : "r"(a[0]), "r"(a[1]), "r"(a[2]), "r"(a[3]), "r"(b[0]), "r"(b[1]));
}

// ---------------- #1 detect index dtype --------------------------------------
__global__ void detect_kernel(const void* node_idx) {
    const unsigned long long* q = (const unsigned long long*)node_idx;
    int is64 = 1;
    #pragma unroll 8
    for (int i = 0; i < 64; i++)
        if (q[i] >= (1ull << 32)) is64 = 0;
    g_is64 = is64;
}

// ---------------- #2 zero counters -------------------------------------------
__global__ void zero_kernel() {
    int i = blockIdx.x * blockDim.x + threadIdx.x;
    if (i < N_NODES) { g_deg_v[i] = 0; g_cur_n[i] = 0; }
    if (i < N_EDGES) { g_deg_e[i] = 0; g_cur_e[i] = 0; }
}

// ---------------- #3 degree histogram ----------------------------------------
__global__ void count_kernel(const void* ni, const void* ei) {
    int i = blockIdx.x * blockDim.x + threadIdx.x;
    if (i >= NNZ) return;
    int is64 = g_is64;
    atomicAdd(&g_deg_v[idx_at(ni, i, is64)], 1);
    atomicAdd(&g_deg_e[idx_at(ei, i, is64)], 1);
}

// ---------------- #4 convert X -> bf16 hi/lo (padded) ------------------------
__global__ void convert_x_kernel(const float* __restrict__ X) {
    int i = blockIdx.x * blockDim.x + threadIdx.x;     // one float4 per thread
    if (i >= N_PAD * DIM / 4) return;
    int row = i >> 6;                                  // /(DIM/4)
    float4 v = make_float4(0.f, 0.f, 0.f, 0.f);
    if (row < N_NODES) v = *(const float4*)&X[(size_t)i * 4];
    float vf[4] = {v.x, v.y, v.z, v.w};
    __nv_bfloat16 hi[4], lo[4];
    #pragma unroll
    for (int k = 0; k < 4; k++) {
        hi[k] = __float2bfloat16_rn(vf[k]);
        lo[k] = __float2bfloat16_rn(vf[k] - __bfloat162float(hi[k]));
    }
    *(uint2*)&g_Xhi[(size_t)i * 4] = *(uint2*)hi;
    *(uint2*)&g_Xlo[(size_t)i * 4] = *(uint2*)lo;
}

// ---------------- #5 convert W -> transposed bf16 hi/lo ----------------------
__global__ void convert_w_kernel(const float* __restrict__ W) {
    int n = blockIdx.x;          // 256 blocks
    int k = threadIdx.x;         // 256 threads
    float w = W[(size_t)k * DIM + n];
    __nv_bfloat16 hi = __float2bfloat16_rn(w);
    __nv_bfloat16 lo = __float2bfloat16_rn(w - __bfloat162float(hi));
    g_Wthi[n * DIM + k] = hi;
    g_Wtlo[n * DIM + k] = lo;
}

// ---------------- #6 GEMM (tensor cores, split bf16): Z = X @ W + b ----------
// 128x128 tile, K-chunks of 32, 8 warps (2m x 4n), each warp 64x32.
#define SA 40
__global__ __launch_bounds__(256, 2)
void gemm_bf16_kernel(const float* __restrict__ bias) {
    __shared__ __align__(16) __nv_bfloat16 As_hi[128][SA];
    __shared__ __align__(16) __nv_bfloat16 As_lo[128][SA];
    __shared__ __align__(16) __nv_bfloat16 Bs_hi[128][SA];
    __shared__ __align__(16) __nv_bfloat16 Bs_lo[128][SA];

    int t    = threadIdx.x;
    int warp = t >> 5, lane = t & 31;
    int wm = warp >> 2, wn = warp & 3;
    int g  = lane >> 2, q = lane & 3;
    int m0 = blockIdx.x * 128;
    int n0 = blockIdx.y * 128;

    float acc[4][4][4];
    #pragma unroll
    for (int i = 0; i < 4; i++)
        #pragma unroll
        for (int j = 0; j < 4; j++)
            #pragma unroll
            for (int r = 0; r < 4; r++) acc[i][j][r] = 0.0f;

    int lrow = t >> 1;        // 0..127
    int lseg = t & 1;         // 16-element segment

    for (int k0 = 0; k0 < DIM; k0 += 32) {
        // load A tile (128 x 32) hi+lo
        {
            const uint4* src = (const uint4*)&g_Xhi[(size_t)(m0 + lrow) * DIM + k0 + lseg * 16];
            uint4 v0 = src[0], v1 = src[1];
            *(uint4*)&As_hi[lrow][lseg * 16]     = v0;
            *(uint4*)&As_hi[lrow][lseg * 16 + 8] = v1;
            const uint4* srl = (const uint4*)&g_Xlo[(size_t)(m0 + lrow) * DIM + k0 + lseg * 16];
            uint4 u0 = srl[0], u1 = srl[1];
            *(uint4*)&As_lo[lrow][lseg * 16]     = u0;
            *(uint4*)&As_lo[lrow][lseg * 16 + 8] = u1;
        }
        // load B tile (128 n x 32 k) hi+lo from transposed W
        {
            const uint4* src = (const uint4*)&g_Wthi[(n0 + lrow) * DIM + k0 + lseg * 16];
            uint4 v0 = src[0], v1 = src[1];
            *(uint4*)&Bs_hi[lrow][lseg * 16]     = v0;
            *(uint4*)&Bs_hi[lrow][lseg * 16 + 8] = v1;
            const uint4* srl = (const uint4*)&g_Wtlo[(n0 + lrow) * DIM + k0 + lseg * 16];
            uint4 u0 = srl[0], u1 = srl[1];
            *(uint4*)&Bs_lo[lrow][lseg * 16]     = u0;
            *(uint4*)&Bs_lo[lrow][lseg * 16 + 8] = u1;
        }
        __syncthreads();

        #pragma unroll
        for (int ksub = 0; ksub < 32; ksub += 16) {
            // B fragments for the 4 n-subtiles
            uint32_t bh[4][2], bl[4][2];
            #pragma unroll
            for (int j = 0; j < 4; j++) {
                int nr = wn * 32 + j * 8 + g;
                int kc = ksub + q * 2;
                bh[j][0] = *(const uint32_t*)&Bs_hi[nr][kc];
                bh[j][1] = *(const uint32_t*)&Bs_hi[nr][kc + 8];
                bl[j][0] = *(const uint32_t*)&Bs_lo[nr][kc];
                bl[j][1] = *(const uint32_t*)&Bs_lo[nr][kc + 8];
            }
            #pragma unroll
            for (int i = 0; i < 4; i++) {
                int mr = wm * 64 + i * 16 + g;
                int kc = ksub + q * 2;
                uint32_t ah[4], al[4];
                ah[0] = *(const uint32_t*)&As_hi[mr][kc];
                ah[1] = *(const uint32_t*)&As_hi[mr + 8][kc];
                ah[2] = *(const uint32_t*)&As_hi[mr][kc + 8];
                ah[3] = *(const uint32_t*)&As_hi[mr + 8][kc + 8];
                al[0] = *(const uint32_t*)&As_lo[mr][kc];
                al[1] = *(const uint32_t*)&As_lo[mr + 8][kc];
                al[2] = *(const uint32_t*)&As_lo[mr][kc + 8];
                al[3] = *(const uint32_t*)&As_lo[mr + 8][kc + 8];
                #pragma unroll
                for (int j = 0; j < 4; j++) {
                    mma16816(acc[i][j], ah, bh[j]);
                    mma16816(acc[i][j], ah, bl[j]);
                    mma16816(acc[i][j], al, bh[j]);
                }
            }
        }
        __syncthreads();
    }

    // epilogue: + bias, store fp32 Z
    #pragma unroll
    for (int j = 0; j < 4; j++) {
        int cb = n0 + wn * 32 + j * 8 + q * 2;
        float2 bb = *(const float2*)&bias[cb];
        #pragma unroll
        for (int i = 0; i < 4; i++) {
            int r = m0 + wm * 64 + i * 16 + g;
            if (r < N_NODES) {
                float2 o0; o0.x = acc[i][j][0] + bb.x; o0.y = acc[i][j][1] + bb.y;
                *(float2*)&g_Z[(size_t)r * DIM + cb] = o0;
            }
            if (r + 8 < N_NODES) {
                float2 o1; o1.x = acc[i][j][2] + bb.x; o1.y = acc[i][j][3] + bb.y;
                *(float2*)&g_Z[(size_t)(r + 8) * DIM + cb] = o1;
            }
        }
    }
}

// ---------------- #7 scan phase 1 --------------------------------------------
__global__ void scan_p1_kernel() {
    int which = blockIdx.y;
    int n          = which ? N_NODES : N_EDGES;
    const int* deg = which ? g_deg_v : g_deg_e;
    int*  off      = which ? g_off_n : g_off_e;
    float* dinv    = which ? g_dv    : g_de;
    int*  part     = which ? g_part_n : g_part_e;

    int base = blockIdx.x * 1024;
    if (base >= n) return;
    int tid = threadIdx.x;
    int i = base + tid;
    int v = (i < n) ? deg[i] : 0;

    int x = v;
    int lane = tid & 31, warp = tid >> 5;
    #pragma unroll
    for (int s = 1; s < 32; s <<= 1) {
        int t = __shfl_up_sync(0xffffffffu, x, s);
        if (lane >= s) x += t;
    }
    __shared__ int wsum[32];
    if (lane == 31) wsum[warp] = x;
    __syncthreads();
    if (warp == 0) {
        int y = wsum[lane];
        #pragma unroll
        for (int s = 1; s < 32; s <<= 1) {
            int t = __shfl_up_sync(0xffffffffu, y, s);
            if (lane >= s) y += t;
        }
        wsum[lane] = y;
    }
    __syncthreads();
    int incl = x + (warp ? wsum[warp - 1] : 0);
    if (i < n) {
        off[i] = incl - v;
        dinv[i] = (v > 0) ? (which ? rsqrtf((float)v) : 1.0f / (float)v) : 0.0f;
    }
    if (tid == 1023) part[blockIdx.x] = incl;
}

// ---------------- #8 scan phase 2 --------------------------------------------
__global__ void scan_p2_kernel() {
    __shared__ int pe[32], pn[64];
    int t = threadIdx.x;
    if (t < 32) pe[t] = (t < CH_E) ? g_part_e[t] : 0;
    if (t < 64) pn[t] = (t < CH_N) ? g_part_n[t] : 0;
    __syncthreads();
    #pragma unroll
    for (int s = 1; s < 64; s <<= 1) {
        int ve = (t < 32 && t >= s) ? pe[t - s] : 0;
        int vn = (t < 64 && t >= s) ? pn[t - s] : 0;
        __syncthreads();
        if (t < 32) pe[t] += ve;
        if (t < 64) pn[t] += vn;
        __syncthreads();
    }
    if (t < 32) g_part_e[t] = t ? pe[t - 1] : 0;
    if (t < 64) g_part_n[t] = t ? pn[t - 1] : 0;
    if (t == 0) { g_off_e[N_EDGES] = NNZ; g_off_n[N_NODES] = NNZ; }
}

// ---------------- #9 scan phase 3 --------------------------------------------
__global__ void scan_p3_kernel() {
    int which = blockIdx.y;
    int n    = which ? N_NODES : N_EDGES;
    int* off = which ? g_off_n : g_off_e;
    int i = blockIdx.x * 1024 + threadIdx.x;
    if (i < n) off[i] += (which ? g_part_n : g_part_e)[blockIdx.x];
}

// ---------------- #10 CSR fill ------------------------------------------------
__global__ void fill_kernel(const void* ni, const void* ei) {
    int i = blockIdx.x * blockDim.x + threadIdx.x;
    if (i >= NNZ) return;
    int is64 = g_is64;
    int n = idx_at(ni, i, is64);
    int e = idx_at(ei, i, is64);
    int pe = atomicAdd(&g_cur_e[e], 1);
    g_adj_e[g_off_e[e] + pe] = n;
    int pn = atomicAdd(&g_cur_n[n], 1);
    g_adj_n[g_off_n[n] + pn] = e;
}

// ---------------- #11 S2[e] = d_e * sum_{n in e} d_v[n] * Z[n] ---------------
__global__ void edge_gather_kernel() {
    int w    = (blockIdx.x * blockDim.x + threadIdx.x) >> 5;
    int lane = threadIdx.x & 31;
    if (w >= N_EDGES) return;
    int s = g_off_e[w], e = g_off_e[w + 1];
    float4 a0 = make_float4(0.f, 0.f, 0.f, 0.f);
    float4 a1 = make_float4(0.f, 0.f, 0.f, 0.f);
    int j = s;
    for (; j + 2 <= e; j += 2) {
        int n0 = g_adj_e[j], n1 = g_adj_e[j + 1];
        float dv0 = g_dv[n0], dv1 = g_dv[n1];
        const float4* p0 = (const float4*)(g_Z + (size_t)n0 * DIM);
        const float4* p1 = (const float4*)(g_Z + (size_t)n1 * DIM);
        float4 v00 = p0[lane], v01 = p0[lane + 32];
        float4 v10 = p1[lane], v11 = p1[lane + 32];
        a0 = f4fma(a0, v00, dv0); a1 = f4fma(a1, v01, dv0);
        a0 = f4fma(a0, v10, dv1); a1 = f4fma(a1, v11, dv1);
    }
    if (j < e) {
        int n0 = g_adj_e[j];
        float dv0 = g_dv[n0];
        const float4* p0 = (const float4*)(g_Z + (size_t)n0 * DIM);
        a0 = f4fma(a0, p0[lane], dv0);
        a1 = f4fma(a1, p0[lane + 32], dv0);
    }
    float de = g_de[w];
    float4* out = (float4*)(g_S2 + (size_t)w * DIM);
    out[lane]      = f4scale(a0, de);
    out[lane + 32] = f4scale(a1, de);
}

// ---------------- #12 out[n] = d_v[n] * sum_{e of n} S2[e] -------------------
__global__ void node_gather_kernel(float* __restrict__ out_g) {
    int w    = (blockIdx.x * blockDim.x + threadIdx.x) >> 5;
    int lane = threadIdx.x & 31;
    if (w >= N_NODES) return;
    int s = g_off_n[w], e = g_off_n[w + 1];
    float4 a0 = make_float4(0.f, 0.f, 0.f, 0.f);
    float4 a1 = make_float4(0.f, 0.f, 0.f, 0.f);
    int j = s;
    for (; j + 2 <= e; j += 2) {
        int e0 = g_adj_n[j], e1 = g_adj_n[j + 1];
        const float4* p0 = (const float4*)(g_S2 + (size_t)e0 * DIM);
        const float4* p1 = (const float4*)(g_S2 + (size_t)e1 * DIM);
        float4 v00 = p0[lane], v01 = p0[lane + 32];
        float4 v10 = p1[lane], v11 = p1[lane + 32];
        a0 = f4add(a0, v00); a1 = f4add(a1, v01);
        a0 = f4add(a0, v10); a1 = f4add(a1, v11);
    }
    if (j < e) {
        int e0 = g_adj_n[j];
        const float4* p0 = (const float4*)(g_S2 + (size_t)e0 * DIM);
        a0 = f4add(a0, p0[lane]);
        a1 = f4add(a1, p0[lane + 32]);
    }
    float dv = g_dv[w];
    float4* out = (float4*)(out_g + (size_t)w * DIM);
    out[lane]      = f4scale(a0, dv);
    out[lane + 32] = f4scale(a1, dv);
}

// ---------------- launch ------------------------------------------------------
extern "C" void kernel_launch(void* const* d_in, const int* in_sizes, int n_in,
                              void* d_out, int out_size) {
    const float* X  = (const float*)d_in[0];
    const void*  ni = d_in[1];
    const void*  ei = d_in[2];
    const float* W  = (const float*)d_in[3];
    const float* b  = (const float*)d_in[4];
    float* out = (float*)d_out;

    detect_kernel<<<1, 1>>>(ni);                                       // 1
    zero_kernel<<<(N_NODES + 255) / 256, 256>>>();                     // 2
    count_kernel<<<(NNZ + 255) / 256, 256>>>(ni, ei);                  // 3
    convert_x_kernel<<<(N_PAD * DIM / 4 + 255) / 256, 256>>>(X);       // 4
    convert_w_kernel<<<DIM, DIM>>>(W);                                 // 5

    dim3 ggrid(N_PAD / 128, DIM / 128);
    gemm_bf16_kernel<<<ggrid, 256>>>(b);                               // 6 (profiled)

    scan_p1_kernel<<<dim3(CH_N, 2), 1024>>>();                         // 7
    scan_p2_kernel<<<1, 128>>>();                                      // 8
    scan_p3_kernel<<<dim3(CH_N, 2), 1024>>>();                         // 9
    fill_kernel<<<(NNZ + 255) / 256, 256>>>(ni, ei);                   // 10
    edge_gather_kernel<<<(N_EDGES * 32 + 255) / 256, 256>>>();         // 11
    node_gather_kernel<<<(N_NODES * 32 + 255) / 256, 256>>>(out);      // 12
}

// round 5
// speedup vs baseline: 1.8364x; 1.1721x over previous
#include <cuda_runtime.h>
#include <cuda_bf16.h>
#include <cstdint>

#define N_NODES 50000
#define N_PAD   50048              // 391 * 128
#define N_EDGES 25000
#define NNZ     800000
#define DIM     256

#define CH_E ((N_EDGES + 1023) / 1024)   // 25
#define CH_N ((N_NODES + 1023) / 1024)   // 49

// ---------------- scratch ----------------------------------------------------
__device__ __align__(16) float g_Z [N_NODES * DIM];     // X@W + b
__device__ __align__(16) float g_S2[N_EDGES * DIM];
__device__ __align__(16) __nv_bfloat16 g_Wthi[DIM * DIM];  // [n][k]
__device__ __align__(16) __nv_bfloat16 g_Wtlo[DIM * DIM];  // [n][k]
__device__ int   g_deg_v[N_NODES];
__device__ int   g_deg_e[N_EDGES];
__device__ float g_dv[N_NODES];
__device__ float g_de[N_EDGES];
__device__ int   g_off_e[N_EDGES + 1];
__device__ int   g_off_n[N_NODES + 1];
__device__ int   g_cur_e[N_EDGES];
__device__ int   g_cur_n[N_NODES];
__device__ int   g_adj_e[NNZ];
__device__ int   g_adj_n[NNZ];
__device__ int   g_part_e[32];
__device__ int   g_part_n[64];
__device__ int   g_is64;

// ---------------- helpers ----------------------------------------------------
__device__ __forceinline__ int idx_at(const void* p, int i, int is64) {
    if (is64) return (int)(((const long long*)p)[i]);
    return ((const int*)p)[i];
}
__device__ __forceinline__ float4 f4add(float4 a, float4 b) {
    a.x += b.x; a.y += b.y; a.z += b.z; a.w += b.w; return a;
}
__device__ __forceinline__ float4 f4fma(float4 a, float4 v, float s) {
    a.x = fmaf(v.x, s, a.x); a.y = fmaf(v.y, s, a.y);
    a.z = fmaf(v.z, s, a.z); a.w = fmaf(v.w, s, a.w); return a;
}
__device__ __forceinline__ float4 f4scale(float4 a, float s) {
    a.x *= s; a.y *= s; a.z *= s; a.w *= s; return a;
}
__device__ __forceinline__ void mma16816(float* c, const uint32_t* a, const uint32_t* b) {
    asm volatile(
        "mma.sync.aligned.m16n8k16.row.col.f32.bf16.bf16.f32 "
        "{%0,%1,%2,%3}, {%4,%5,%6,%7}, {%8,%9}, {%0,%1,%2,%3};\n"
        : "+f"(c[0]), "+f"(c[1]), "+f"(c[2]), "+f"(c[3])
        : "r"(a[0]), "r"(a[1]), "r"(a[2]), "r"(a[3]), "r"(b[0]), "r"(b[1]));
}

// ---------------- detect index dtype -----------------------------------------
__global__ void detect_kernel(const void* node_idx) {
    const unsigned long long* q = (const unsigned long long*)node_idx;
    int is64 = 1;
    #pragma unroll 8
    for (int i = 0; i < 64; i++)
        if (q[i] >= (1ull << 32)) is64 = 0;
    g_is64 = is64;
}

// ---------------- zero counters ----------------------------------------------
__global__ void zero_kernel() {
    int i = blockIdx.x * blockDim.x + threadIdx.x;
    if (i < N_NODES) { g_deg_v[i] = 0; g_cur_n[i] = 0; }
    if (i < N_EDGES) { g_deg_e[i] = 0; g_cur_e[i] = 0; }
}

// ---------------- degree histogram -------------------------------------------
__global__ void count_kernel(const void* ni, const void* ei) {
    int i = blockIdx.x * blockDim.x + threadIdx.x;
    if (i >= NNZ) return;
    int is64 = g_is64;
    atomicAdd(&g_deg_v[idx_at(ni, i, is64)], 1);
    atomicAdd(&g_deg_e[idx_at(ei, i, is64)], 1);
}

// ---------------- convert W -> transposed bf16 hi/lo -------------------------
__global__ void convert_w_kernel(const float* __restrict__ W) {
    int n = blockIdx.x;          // 256 blocks
    int k = threadIdx.x;         // 256 threads
    float w = W[(size_t)k * DIM + n];
    __nv_bfloat16 hi = __float2bfloat16_rn(w);
    __nv_bfloat16 lo = __float2bfloat16_rn(w - __bfloat162float(hi));
    g_Wthi[n * DIM + k] = hi;
    g_Wtlo[n * DIM + k] = lo;
}

// ---------------- GEMM (tensor cores, split bf16, fused conversion) ----------
// Z = X @ W + b.  128x128 tile, K-chunks of 32, 8 warps (2m x 4n).
#define SA 40
__global__ __launch_bounds__(256, 2)
void gemm_bf16_kernel(const float* __restrict__ X,
                      const float* __restrict__ bias) {
    __shared__ __align__(16) __nv_bfloat16 As_hi[128][SA];
    __shared__ __align__(16) __nv_bfloat16 As_lo[128][SA];
    __shared__ __align__(16) __nv_bfloat16 Bs_hi[128][SA];
    __shared__ __align__(16) __nv_bfloat16 Bs_lo[128][SA];

    int t    = threadIdx.x;
    int warp = t >> 5, lane = t & 31;
    int wm = warp >> 2, wn = warp & 3;
    int g  = lane >> 2, q = lane & 3;
    int m0 = blockIdx.x * 128;
    int n0 = blockIdx.y * 128;

    float acc[4][4][4];
    #pragma unroll
    for (int i = 0; i < 4; i++)
        #pragma unroll
        for (int j = 0; j < 4; j++)
            #pragma unroll
            for (int r = 0; r < 4; r++) acc[i][j][r] = 0.0f;

    int lrow = t >> 1;        // 0..127
    int lseg = t & 1;         // 16-element segment

    for (int k0 = 0; k0 < DIM; k0 += 32) {
        // A tile (128 x 32): load fp32 X, split to bf16 hi/lo on the fly
        {
            int gr = m0 + lrow;
            float vf[16];
            if (gr < N_NODES) {
                const float4* src = (const float4*)&X[(size_t)gr * DIM + k0 + lseg * 16];
                float4 f0 = src[0], f1 = src[1], f2 = src[2], f3 = src[3];
                vf[0]=f0.x; vf[1]=f0.y; vf[2]=f0.z; vf[3]=f0.w;
                vf[4]=f1.x; vf[5]=f1.y; vf[6]=f1.z; vf[7]=f1.w;
                vf[8]=f2.x; vf[9]=f2.y; vf[10]=f2.z; vf[11]=f2.w;
                vf[12]=f3.x; vf[13]=f3.y; vf[14]=f3.z; vf[15]=f3.w;
            } else {
                #pragma unroll
                for (int k = 0; k < 16; k++) vf[k] = 0.0f;
            }
            __nv_bfloat16 hi[16], lo[16];
            #pragma unroll
            for (int k = 0; k < 16; k++) {
                hi[k] = __float2bfloat16_rn(vf[k]);
                lo[k] = __float2bfloat16_rn(vf[k] - __bfloat162float(hi[k]));
            }
            *(uint4*)&As_hi[lrow][lseg * 16]     = ((uint4*)hi)[0];
            *(uint4*)&As_hi[lrow][lseg * 16 + 8] = ((uint4*)hi)[1];
            *(uint4*)&As_lo[lrow][lseg * 16]     = ((uint4*)lo)[0];
            *(uint4*)&As_lo[lrow][lseg * 16 + 8] = ((uint4*)lo)[1];
        }
        // B tile (128 n x 32 k) from transposed bf16 W
        {
            const uint4* src = (const uint4*)&g_Wthi[(n0 + lrow) * DIM + k0 + lseg * 16];
            uint4 v0 = src[0], v1 = src[1];
            *(uint4*)&Bs_hi[lrow][lseg * 16]     = v0;
            *(uint4*)&Bs_hi[lrow][lseg * 16 + 8] = v1;
            const uint4* srl = (const uint4*)&g_Wtlo[(n0 + lrow) * DIM + k0 + lseg * 16];
            uint4 u0 = srl[0], u1 = srl[1];
            *(uint4*)&Bs_lo[lrow][lseg * 16]     = u0;
            *(uint4*)&Bs_lo[lrow][lseg * 16 + 8] = u1;
        }
        __syncthreads();

        #pragma unroll
        for (int ksub = 0; ksub < 32; ksub += 16) {
            uint32_t bh[4][2], bl[4][2];
            #pragma unroll
            for (int j = 0; j < 4; j++) {
                int nr = wn * 32 + j * 8 + g;
                int kc = ksub + q * 2;
                bh[j][0] = *(const uint32_t*)&Bs_hi[nr][kc];
                bh[j][1] = *(const uint32_t*)&Bs_hi[nr][kc + 8];
                bl[j][0] = *(const uint32_t*)&Bs_lo[nr][kc];
                bl[j][1] = *(const uint32_t*)&Bs_lo[nr][kc + 8];
            }
            #pragma unroll
            for (int i = 0; i < 4; i++) {
                int mr = wm * 64 + i * 16 + g;
                int kc = ksub + q * 2;
                uint32_t ah[4], al[4];
                ah[0] = *(const uint32_t*)&As_hi[mr][kc];
                ah[1] = *(const uint32_t*)&As_hi[mr + 8][kc];
                ah[2] = *(const uint32_t*)&As_hi[mr][kc + 8];
                ah[3] = *(const uint32_t*)&As_hi[mr + 8][kc + 8];
                al[0] = *(const uint32_t*)&As_lo[mr][kc];
                al[1] = *(const uint32_t*)&As_lo[mr + 8][kc];
                al[2] = *(const uint32_t*)&As_lo[mr][kc + 8];
                al[3] = *(const uint32_t*)&As_lo[mr + 8][kc + 8];
                #pragma unroll
                for (int j = 0; j < 4; j++) {
                    mma16816(acc[i][j], ah, bh[j]);
                    mma16816(acc[i][j], ah, bl[j]);
                    mma16816(acc[i][j], al, bh[j]);
                }
            }
        }
        __syncthreads();
    }

    #pragma unroll
    for (int j = 0; j < 4; j++) {
        int cb = n0 + wn * 32 + j * 8 + q * 2;
        float2 bb = *(const float2*)&bias[cb];
        #pragma unroll
        for (int i = 0; i < 4; i++) {
            int r = m0 + wm * 64 + i * 16 + g;
            if (r < N_NODES) {
                float2 o0; o0.x = acc[i][j][0] + bb.x; o0.y = acc[i][j][1] + bb.y;
                *(float2*)&g_Z[(size_t)r * DIM + cb] = o0;
            }
            if (r + 8 < N_NODES) {
                float2 o1; o1.x = acc[i][j][2] + bb.x; o1.y = acc[i][j][3] + bb.y;
                *(float2*)&g_Z[(size_t)(r + 8) * DIM + cb] = o1;
            }
        }
    }
}

// ---------------- scan phase 1 -----------------------------------------------
__global__ void scan_p1_kernel() {
    int which = blockIdx.y;
    int n          = which ? N_NODES : N_EDGES;
    const int* deg = which ? g_deg_v : g_deg_e;
    int*  off      = which ? g_off_n : g_off_e;
    float* dinv    = which ? g_dv    : g_de;
    int*  part     = which ? g_part_n : g_part_e;

    int base = blockIdx.x * 1024;
    if (base >= n) return;
    int tid = threadIdx.x;
    int i = base + tid;
    int v = (i < n) ? deg[i] : 0;

    int x = v;
    int lane = tid & 31, warp = tid >> 5;
    #pragma unroll
    for (int s = 1; s < 32; s <<= 1) {
        int t = __shfl_up_sync(0xffffffffu, x, s);
        if (lane >= s) x += t;
    }
    __shared__ int wsum[32];
    if (lane == 31) wsum[warp] = x;
    __syncthreads();
    if (warp == 0) {
        int y = wsum[lane];
        #pragma unroll
        for (int s = 1; s < 32; s <<= 1) {
            int t = __shfl_up_sync(0xffffffffu, y, s);
            if (lane >= s) y += t;
        }
        wsum[lane] = y;
    }
    __syncthreads();
    int incl = x + (warp ? wsum[warp - 1] : 0);
    if (i < n) {
        off[i] = incl - v;
        dinv[i] = (v > 0) ? (which ? rsqrtf((float)v) : 1.0f / (float)v) : 0.0f;
    }
    if (tid == 1023) part[blockIdx.x] = incl;
}

// ---------------- scan phase 2 -----------------------------------------------
__global__ void scan_p2_kernel() {
    __shared__ int pe[32], pn[64];
    int t = threadIdx.x;
    if (t < 32) pe[t] = (t < CH_E) ? g_part_e[t] : 0;
    if (t < 64) pn[t] = (t < CH_N) ? g_part_n[t] : 0;
    __syncthreads();
    #pragma unroll
    for (int s = 1; s < 64; s <<= 1) {
        int ve = (t < 32 && t >= s) ? pe[t - s] : 0;
        int vn = (t < 64 && t >= s) ? pn[t - s] : 0;
        __syncthreads();
        if (t < 32) pe[t] += ve;
        if (t < 64) pn[t] += vn;
        __syncthreads();
    }
    if (t < 32) g_part_e[t] = t ? pe[t - 1] : 0;
    if (t < 64) g_part_n[t] = t ? pn[t - 1] : 0;
    if (t == 0) { g_off_e[N_EDGES] = NNZ; g_off_n[N_NODES] = NNZ; }
}

// ---------------- scan phase 3 -----------------------------------------------
__global__ void scan_p3_kernel() {
    int which = blockIdx.y;
    int n    = which ? N_NODES : N_EDGES;
    int* off = which ? g_off_n : g_off_e;
    int i = blockIdx.x * 1024 + threadIdx.x;
    if (i < n) off[i] += (which ? g_part_n : g_part_e)[blockIdx.x];
}

// ---------------- CSR fill ----------------------------------------------------
__global__ void fill_kernel(const void* ni, const void* ei) {
    int i = blockIdx.x * blockDim.x + threadIdx.x;
    if (i >= NNZ) return;
    int is64 = g_is64;
    int n = idx_at(ni, i, is64);
    int e = idx_at(ei, i, is64);
    int pe = atomicAdd(&g_cur_e[e], 1);
    g_adj_e[g_off_e[e] + pe] = n;
    int pn = atomicAdd(&g_cur_n[n], 1);
    g_adj_n[g_off_n[n] + pn] = e;
}

// ---------------- S2[e] = d_e * sum_{n in e} d_v[n] * Z[n] -------------------
__global__ void edge_gather_kernel() {
    int w    = (blockIdx.x * blockDim.x + threadIdx.x) >> 5;
    int lane = threadIdx.x & 31;
    if (w >= N_EDGES) return;
    int s = g_off_e[w], e = g_off_e[w + 1];
    float4 a0 = make_float4(0.f, 0.f, 0.f, 0.f);
    float4 a1 = make_float4(0.f, 0.f, 0.f, 0.f);
    int j = s;
    for (; j + 4 <= e; j += 4) {
        int n0 = g_adj_e[j],     n1 = g_adj_e[j + 1];
        int n2 = g_adj_e[j + 2], n3 = g_adj_e[j + 3];
        float d0 = g_dv[n0], d1 = g_dv[n1], d2 = g_dv[n2], d3 = g_dv[n3];
        const float4* p0 = (const float4*)(g_Z + (size_t)n0 * DIM);
        const float4* p1 = (const float4*)(g_Z + (size_t)n1 * DIM);
        const float4* p2 = (const float4*)(g_Z + (size_t)n2 * DIM);
        const float4* p3 = (const float4*)(g_Z + (size_t)n3 * DIM);
        float4 v0a = p0[lane], v0b = p0[lane + 32];
        float4 v1a = p1[lane], v1b = p1[lane + 32];
        float4 v2a = p2[lane], v2b = p2[lane + 32];
        float4 v3a = p3[lane], v3b = p3[lane + 32];
        a0 = f4fma(a0, v0a, d0); a1 = f4fma(a1, v0b, d0);
        a0 = f4fma(a0, v1a, d1); a1 = f4fma(a1, v1b, d1);
        a0 = f4fma(a0, v2a, d2); a1 = f4fma(a1, v2b, d2);
        a0 = f4fma(a0, v3a, d3); a1 = f4fma(a1, v3b, d3);
    }
    for (; j < e; j++) {
        int n0 = g_adj_e[j];
        float d0 = g_dv[n0];
        const float4* p0 = (const float4*)(g_Z + (size_t)n0 * DIM);
        a0 = f4fma(a0, p0[lane], d0);
        a1 = f4fma(a1, p0[lane + 32], d0);
    }
    float de = g_de[w];
    float4* out = (float4*)(g_S2 + (size_t)w * DIM);
    out[lane]      = f4scale(a0, de);
    out[lane + 32] = f4scale(a1, de);
}

// ---------------- out[n] = d_v[n] * sum_{e of n} S2[e] -----------------------
__global__ void node_gather_kernel(float* __restrict__ out_g) {
    int w    = (blockIdx.x * blockDim.x + threadIdx.x) >> 5;
    int lane = threadIdx.x & 31;
    if (w >= N_NODES) return;
    int s = g_off_n[w], e = g_off_n[w + 1];
    float4 a0 = make_float4(0.f, 0.f, 0.f, 0.f);
    float4 a1 = make_float4(0.f, 0.f, 0.f, 0.f);
    int j = s;
    for (; j + 4 <= e; j += 4) {
        int e0 = g_adj_n[j],     e1 = g_adj_n[j + 1];
        int e2 = g_adj_n[j + 2], e3 = g_adj_n[j + 3];
        const float4* p0 = (const float4*)(g_S2 + (size_t)e0 * DIM);
        const float4* p1 = (const float4*)(g_S2 + (size_t)e1 * DIM);
        const float4* p2 = (const float4*)(g_S2 + (size_t)e2 * DIM);
        const float4* p3 = (const float4*)(g_S2 + (size_t)e3 * DIM);
        float4 v0a = p0[lane], v0b = p0[lane + 32];
        float4 v1a = p1[lane], v1b = p1[lane + 32];
        float4 v2a = p2[lane], v2b = p2[lane + 32];
        float4 v3a = p3[lane], v3b = p3[lane + 32];
        a0 = f4add(a0, v0a); a1 = f4add(a1, v0b);
        a0 = f4add(a0, v1a); a1 = f4add(a1, v1b);
        a0 = f4add(a0, v2a); a1 = f4add(a1, v2b);
        a0 = f4add(a0, v3a); a1 = f4add(a1, v3b);
    }
    for (; j < e; j++) {
        int e0 = g_adj_n[j];
        const float4* p0 = (const float4*)(g_S2 + (size_t)e0 * DIM);
        a0 = f4add(a0, p0[lane]);
        a1 = f4add(a1, p0[lane + 32]);
    }
    float dv = g_dv[w];
    float4* out = (float4*)(out_g + (size_t)w * DIM);
    out[lane]      = f4scale(a0, dv);
    out[lane + 32] = f4scale(a1, dv);
}

// ---------------- launch (fork/join: CSR chain || GEMM chain) ----------------
extern "C" void kernel_launch(void* const* d_in, const int* in_sizes, int n_in,
                              void* d_out, int out_size) {
    const float* X  = (const float*)d_in[0];
    const void*  ni = d_in[1];
    const void*  ei = d_in[2];
    const float* W  = (const float*)d_in[3];
    const float* b  = (const float*)d_in[4];
    float* out = (float*)d_out;

    static cudaStream_t sB = nullptr;
    static cudaEvent_t evRoot = nullptr, evB = nullptr;
    if (sB == nullptr) {
        cudaStreamCreateWithFlags(&sB, cudaStreamNonBlocking);
        cudaEventCreateWithFlags(&evRoot, cudaEventDisableTiming);
        cudaEventCreateWithFlags(&evB, cudaEventDisableTiming);
    }

    // fork: stream sB branches off the main (capture) stream
    cudaEventRecord(evRoot, 0);
    cudaStreamWaitEvent(sB, evRoot, 0);

    // ---- chain B (stream sB): W convert + GEMM (fused X conversion) ----
    convert_w_kernel<<<DIM, DIM, 0, sB>>>(W);
    dim3 ggrid(N_PAD / 128, DIM / 128);
    gemm_bf16_kernel<<<ggrid, 256, 0, sB>>>(X, b);

    // ---- chain A (main stream): CSR build ----
    detect_kernel<<<1, 1>>>(ni);
    zero_kernel<<<(N_NODES + 255) / 256, 256>>>();
    count_kernel<<<(NNZ + 255) / 256, 256>>>(ni, ei);
    scan_p1_kernel<<<dim3(CH_N, 2), 1024>>>();
    scan_p2_kernel<<<1, 128>>>();
    scan_p3_kernel<<<dim3(CH_N, 2), 1024>>>();
    fill_kernel<<<(NNZ + 255) / 256, 256>>>(ni, ei);

    // join: main stream waits for chain B
    cudaEventRecord(evB, sB);
    cudaStreamWaitEvent(0, evB, 0);

    edge_gather_kernel<<<(N_EDGES * 32 + 255) / 256, 256>>>();
    node_gather_kernel<<<(N_NODES * 32 + 255) / 256, 256>>>(out);
}

// round 6
// speedup vs baseline: 2.1741x; 1.1839x over previous
#include <cuda_runtime.h>
#include <cuda_bf16.h>
#include <cuda_fp16.h>
#include <cstdint>

#define N_NODES 50000
#define N_PAD   50048              // 391 * 128
#define N_EDGES 25000
#define NNZ     800000
#define DIM     256

#define CH_E ((N_EDGES + 1023) / 1024)   // 25
#define CH_N ((N_NODES + 1023) / 1024)   // 49

// ---------------- scratch ----------------------------------------------------
__device__ __align__(16) __half g_Zh [N_NODES * DIM];     // fp16(X@W + b)  25.6MB
__device__ __align__(16) __half g_S2h[N_EDGES * DIM];     // fp16 step2     12.8MB
__device__ __align__(16) __nv_bfloat16 g_Wthi[DIM * DIM]; // [n][k]
__device__ __align__(16) __nv_bfloat16 g_Wtlo[DIM * DIM]; // [n][k]
__device__ int   g_deg_v[N_NODES];
__device__ int   g_deg_e[N_EDGES];
__device__ float g_dv[N_NODES];
__device__ float g_de[N_EDGES];
__device__ int   g_off_e[N_EDGES + 1];
__device__ int   g_off_n[N_NODES + 1];
__device__ int   g_cur_e[N_EDGES];
__device__ int   g_cur_n[N_NODES];
__device__ int   g_adj_e[NNZ];
__device__ int   g_adj_n[NNZ];
__device__ int   g_part_e[32];
__device__ int   g_part_n[64];
__device__ int   g_is64;

// ---------------- helpers ----------------------------------------------------
__device__ __forceinline__ int idx_at(const void* p, int i, int is64) {
    if (is64) return (int)(((const long long*)p)[i]);
    return ((const int*)p)[i];
}
__device__ __forceinline__ void mma16816(float* c, const uint32_t* a, const uint32_t* b) {
    asm volatile(
        "mma.sync.aligned.m16n8k16.row.col.f32.bf16.bf16.f32 "
        "{%0,%1,%2,%3}, {%4,%5,%6,%7}, {%8,%9}, {%0,%1,%2,%3};\n"
        : "+f"(c[0]), "+f"(c[1]), "+f"(c[2]), "+f"(c[3])
        : "r"(a[0]), "r"(a[1]), "r"(a[2]), "r"(a[3]), "r"(b[0]), "r"(b[1]));
}
// accumulate 8 fp16 lanes (one uint4) into float acc[8], scaled by s
__device__ __forceinline__ void acc8(float* a, uint4 v, float s) {
    __half2 h0 = *(__half2*)&v.x, h1 = *(__half2*)&v.y;
    __half2 h2 = *(__half2*)&v.z, h3 = *(__half2*)&v.w;
    float2 f0 = __half22float2(h0), f1 = __half22float2(h1);
    float2 f2 = __half22float2(h2), f3 = __half22float2(h3);
    a[0] = fmaf(f0.x, s, a[0]); a[1] = fmaf(f0.y, s, a[1]);
    a[2] = fmaf(f1.x, s, a[2]); a[3] = fmaf(f1.y, s, a[3]);
    a[4] = fmaf(f2.x, s, a[4]); a[5] = fmaf(f2.y, s, a[5]);
    a[6] = fmaf(f3.x, s, a[6]); a[7] = fmaf(f3.y, s, a[7]);
}

// ---------------- detect index dtype -----------------------------------------
__global__ void detect_kernel(const void* node_idx) {
    const unsigned long long* q = (const unsigned long long*)node_idx;
    int is64 = 1;
    #pragma unroll 8
    for (int i = 0; i < 64; i++)
        if (q[i] >= (1ull << 32)) is64 = 0;
    g_is64 = is64;
}

// ---------------- zero counters ----------------------------------------------
__global__ void zero_kernel() {
    int i = blockIdx.x * blockDim.x + threadIdx.x;
    if (i < N_NODES) { g_deg_v[i] = 0; g_cur_n[i] = 0; }
    if (i < N_EDGES) { g_deg_e[i] = 0; g_cur_e[i] = 0; }
}

// ---------------- degree histogram -------------------------------------------
__global__ void count_kernel(const void* ni, const void* ei) {
    int i = blockIdx.x * blockDim.x + threadIdx.x;
    if (i >= NNZ) return;
    int is64 = g_is64;
    atomicAdd(&g_deg_v[idx_at(ni, i, is64)], 1);
    atomicAdd(&g_deg_e[idx_at(ei, i, is64)], 1);
}

// ---------------- convert W -> transposed bf16 hi/lo -------------------------
__global__ void convert_w_kernel(const float* __restrict__ W) {
    int n = blockIdx.x;
    int k = threadIdx.x;
    float w = W[(size_t)k * DIM + n];
    __nv_bfloat16 hi = __float2bfloat16_rn(w);
    __nv_bfloat16 lo = __float2bfloat16_rn(w - __bfloat162float(hi));
    g_Wthi[n * DIM + k] = hi;
    g_Wtlo[n * DIM + k] = lo;
}

// ---------------- GEMM (tensor cores, split bf16, fused conversion) ----------
// Zh = fp16(X @ W + b).  128x128 tile, K-chunks of 32, 8 warps (2m x 4n).
#define SA 40
__global__ __launch_bounds__(256, 2)
void gemm_bf16_kernel(const float* __restrict__ X,
                      const float* __restrict__ bias) {
    __shared__ __align__(16) __nv_bfloat16 As_hi[128][SA];
    __shared__ __align__(16) __nv_bfloat16 As_lo[128][SA];
    __shared__ __align__(16) __nv_bfloat16 Bs_hi[128][SA];
    __shared__ __align__(16) __nv_bfloat16 Bs_lo[128][SA];

    int t    = threadIdx.x;
    int warp = t >> 5, lane = t & 31;
    int wm = warp >> 2, wn = warp & 3;
    int g  = lane >> 2, q = lane & 3;
    int m0 = blockIdx.x * 128;
    int n0 = blockIdx.y * 128;

    float acc[4][4][4];
    #pragma unroll
    for (int i = 0; i < 4; i++)
        #pragma unroll
        for (int j = 0; j < 4; j++)
            #pragma unroll
            for (int r = 0; r < 4; r++) acc[i][j][r] = 0.0f;

    int lrow = t >> 1;
    int lseg = t & 1;

    for (int k0 = 0; k0 < DIM; k0 += 32) {
        {
            int gr = m0 + lrow;
            float vf[16];
            if (gr < N_NODES) {
                const float4* src = (const float4*)&X[(size_t)gr * DIM + k0 + lseg * 16];
                float4 f0 = src[0], f1 = src[1], f2 = src[2], f3 = src[3];
                vf[0]=f0.x; vf[1]=f0.y; vf[2]=f0.z; vf[3]=f0.w;
                vf[4]=f1.x; vf[5]=f1.y; vf[6]=f1.z; vf[7]=f1.w;
                vf[8]=f2.x; vf[9]=f2.y; vf[10]=f2.z; vf[11]=f2.w;
                vf[12]=f3.x; vf[13]=f3.y; vf[14]=f3.z; vf[15]=f3.w;
            } else {
                #pragma unroll
                for (int k = 0; k < 16; k++) vf[k] = 0.0f;
            }
            __nv_bfloat16 hi[16], lo[16];
            #pragma unroll
            for (int k = 0; k < 16; k++) {
                hi[k] = __float2bfloat16_rn(vf[k]);
                lo[k] = __float2bfloat16_rn(vf[k] - __bfloat162float(hi[k]));
            }
            *(uint4*)&As_hi[lrow][lseg * 16]     = ((uint4*)hi)[0];
            *(uint4*)&As_hi[lrow][lseg * 16 + 8] = ((uint4*)hi)[1];
            *(uint4*)&As_lo[lrow][lseg * 16]     = ((uint4*)lo)[0];
            *(uint4*)&As_lo[lrow][lseg * 16 + 8] = ((uint4*)lo)[1];
        }
        {
            const uint4* src = (const uint4*)&g_Wthi[(n0 + lrow) * DIM + k0 + lseg * 16];
            uint4 v0 = src[0], v1 = src[1];
            *(uint4*)&Bs_hi[lrow][lseg * 16]     = v0;
            *(uint4*)&Bs_hi[lrow][lseg * 16 + 8] = v1;
            const uint4* srl = (const uint4*)&g_Wtlo[(n0 + lrow) * DIM + k0 + lseg * 16];
            uint4 u0 = srl[0], u1 = srl[1];
            *(uint4*)&Bs_lo[lrow][lseg * 16]     = u0;
            *(uint4*)&Bs_lo[lrow][lseg * 16 + 8] = u1;
        }
        __syncthreads();

        #pragma unroll
        for (int ksub = 0; ksub < 32; ksub += 16) {
            uint32_t bh[4][2], bl[4][2];
            #pragma unroll
            for (int j = 0; j < 4; j++) {
                int nr = wn * 32 + j * 8 + g;
                int kc = ksub + q * 2;
                bh[j][0] = *(const uint32_t*)&Bs_hi[nr][kc];
                bh[j][1] = *(const uint32_t*)&Bs_hi[nr][kc + 8];
                bl[j][0] = *(const uint32_t*)&Bs_lo[nr][kc];
                bl[j][1] = *(const uint32_t*)&Bs_lo[nr][kc + 8];
            }
            #pragma unroll
            for (int i = 0; i < 4; i++) {
                int mr = wm * 64 + i * 16 + g;
                int kc = ksub + q * 2;
                uint32_t ah[4], al[4];
                ah[0] = *(const uint32_t*)&As_hi[mr][kc];
                ah[1] = *(const uint32_t*)&As_hi[mr + 8][kc];
                ah[2] = *(const uint32_t*)&As_hi[mr][kc + 8];
                ah[3] = *(const uint32_t*)&As_hi[mr + 8][kc + 8];
                al[0] = *(const uint32_t*)&As_lo[mr][kc];
                al[1] = *(const uint32_t*)&As_lo[mr + 8][kc];
                al[2] = *(const uint32_t*)&As_lo[mr][kc + 8];
                al[3] = *(const uint32_t*)&As_lo[mr + 8][kc + 8];
                #pragma unroll
                for (int j = 0; j < 4; j++) {
                    mma16816(acc[i][j], ah, bh[j]);
                    mma16816(acc[i][j], ah, bl[j]);
                    mma16816(acc[i][j], al, bh[j]);
                }
            }
        }
        __syncthreads();
    }

    // epilogue: + bias, store fp16 Zh
    #pragma unroll
    for (int j = 0; j < 4; j++) {
        int cb = n0 + wn * 32 + j * 8 + q * 2;
        float2 bb = *(const float2*)&bias[cb];
        #pragma unroll
        for (int i = 0; i < 4; i++) {
            int r = m0 + wm * 64 + i * 16 + g;
            if (r < N_NODES) {
                __half2 o = __floats2half2_rn(acc[i][j][0] + bb.x, acc[i][j][1] + bb.y);
                *(__half2*)&g_Zh[(size_t)r * DIM + cb] = o;
            }
            if (r + 8 < N_NODES) {
                __half2 o = __floats2half2_rn(acc[i][j][2] + bb.x, acc[i][j][3] + bb.y);
                *(__half2*)&g_Zh[(size_t)(r + 8) * DIM + cb] = o;
            }
        }
    }
}

// ---------------- scan phase 1 -----------------------------------------------
__global__ void scan_p1_kernel() {
    int which = blockIdx.y;
    int n          = which ? N_NODES : N_EDGES;
    const int* deg = which ? g_deg_v : g_deg_e;
    int*  off      = which ? g_off_n : g_off_e;
    float* dinv    = which ? g_dv    : g_de;
    int*  part     = which ? g_part_n : g_part_e;

    int base = blockIdx.x * 1024;
    if (base >= n) return;
    int tid = threadIdx.x;
    int i = base + tid;
    int v = (i < n) ? deg[i] : 0;

    int x = v;
    int lane = tid & 31, warp = tid >> 5;
    #pragma unroll
    for (int s = 1; s < 32; s <<= 1) {
        int t = __shfl_up_sync(0xffffffffu, x, s);
        if (lane >= s) x += t;
    }
    __shared__ int wsum[32];
    if (lane == 31) wsum[warp] = x;
    __syncthreads();
    if (warp == 0) {
        int y = wsum[lane];
        #pragma unroll
        for (int s = 1; s < 32; s <<= 1) {
            int t = __shfl_up_sync(0xffffffffu, y, s);
            if (lane >= s) y += t;
        }
        wsum[lane] = y;
    }
    __syncthreads();
    int incl = x + (warp ? wsum[warp - 1] : 0);
    if (i < n) {
        off[i] = incl - v;
        dinv[i] = (v > 0) ? (which ? rsqrtf((float)v) : 1.0f / (float)v) : 0.0f;
    }
    if (tid == 1023) part[blockIdx.x] = incl;
}

// ---------------- scan phase 2 -----------------------------------------------
__global__ void scan_p2_kernel() {
    __shared__ int pe[32], pn[64];
    int t = threadIdx.x;
    if (t < 32) pe[t] = (t < CH_E) ? g_part_e[t] : 0;
    if (t < 64) pn[t] = (t < CH_N) ? g_part_n[t] : 0;
    __syncthreads();
    #pragma unroll
    for (int s = 1; s < 64; s <<= 1) {
        int ve = (t < 32 && t >= s) ? pe[t - s] : 0;
        int vn = (t < 64 && t >= s) ? pn[t - s] : 0;
        __syncthreads();
        if (t < 32) pe[t] += ve;
        if (t < 64) pn[t] += vn;
        __syncthreads();
    }
    if (t < 32) g_part_e[t] = t ? pe[t - 1] : 0;
    if (t < 64) g_part_n[t] = t ? pn[t - 1] : 0;
    if (t == 0) { g_off_e[N_EDGES] = NNZ; g_off_n[N_NODES] = NNZ; }
}

// ---------------- scan phase 3 -----------------------------------------------
__global__ void scan_p3_kernel() {
    int which = blockIdx.y;
    int n    = which ? N_NODES : N_EDGES;
    int* off = which ? g_off_n : g_off_e;
    int i = blockIdx.x * 1024 + threadIdx.x;
    if (i < n) off[i] += (which ? g_part_n : g_part_e)[blockIdx.x];
}

// ---------------- CSR fill ----------------------------------------------------
__global__ void fill_kernel(const void* ni, const void* ei) {
    int i = blockIdx.x * blockDim.x + threadIdx.x;
    if (i >= NNZ) return;
    int is64 = g_is64;
    int n = idx_at(ni, i, is64);
    int e = idx_at(ei, i, is64);
    int pe = atomicAdd(&g_cur_e[e], 1);
    g_adj_e[g_off_e[e] + pe] = n;
    int pn = atomicAdd(&g_cur_n[n], 1);
    g_adj_n[g_off_n[n] + pn] = e;
}

// ---------------- S2h[e] = fp16( d_e * sum_{n in e} d_v[n] * Zh[n] ) ---------
// one warp per edge; lane owns 8 contiguous fp16 columns (one uint4 per row)
__global__ void edge_gather_kernel() {
    int w    = (blockIdx.x * blockDim.x + threadIdx.x) >> 5;
    int lane = threadIdx.x & 31;
    if (w >= N_EDGES) return;
    int s = g_off_e[w], e = g_off_e[w + 1];
    float a[8] = {0.f, 0.f, 0.f, 0.f, 0.f, 0.f, 0.f, 0.f};
    int j = s;
    for (; j + 4 <= e; j += 4) {
        int n0 = g_adj_e[j],     n1 = g_adj_e[j + 1];
        int n2 = g_adj_e[j + 2], n3 = g_adj_e[j + 3];
        float d0 = g_dv[n0], d1 = g_dv[n1], d2 = g_dv[n2], d3 = g_dv[n3];
        uint4 v0 = *(const uint4*)&g_Zh[(size_t)n0 * DIM + lane * 8];
        uint4 v1 = *(const uint4*)&g_Zh[(size_t)n1 * DIM + lane * 8];
        uint4 v2 = *(const uint4*)&g_Zh[(size_t)n2 * DIM + lane * 8];
        uint4 v3 = *(const uint4*)&g_Zh[(size_t)n3 * DIM + lane * 8];
        acc8(a, v0, d0); acc8(a, v1, d1); acc8(a, v2, d2); acc8(a, v3, d3);
    }
    for (; j < e; j++) {
        int n0 = g_adj_e[j];
        float d0 = g_dv[n0];
        uint4 v0 = *(const uint4*)&g_Zh[(size_t)n0 * DIM + lane * 8];
        acc8(a, v0, d0);
    }
    float de = g_de[w];
    __half2 o0 = __floats2half2_rn(a[0] * de, a[1] * de);
    __half2 o1 = __floats2half2_rn(a[2] * de, a[3] * de);
    __half2 o2 = __floats2half2_rn(a[4] * de, a[5] * de);
    __half2 o3 = __floats2half2_rn(a[6] * de, a[7] * de);
    uint4 st;
    st.x = *(uint32_t*)&o0; st.y = *(uint32_t*)&o1;
    st.z = *(uint32_t*)&o2; st.w = *(uint32_t*)&o3;
    *(uint4*)&g_S2h[(size_t)w * DIM + lane * 8] = st;
}

// ---------------- out[n] = d_v[n] * sum_{e of n} S2h[e]  (fp32 out) ----------
__global__ void node_gather_kernel(float* __restrict__ out_g) {
    int w    = (blockIdx.x * blockDim.x + threadIdx.x) >> 5;
    int lane = threadIdx.x & 31;
    if (w >= N_NODES) return;
    int s = g_off_n[w], e = g_off_n[w + 1];
    float a[8] = {0.f, 0.f, 0.f, 0.f, 0.f, 0.f, 0.f, 0.f};
    int j = s;
    for (; j + 4 <= e; j += 4) {
        int e0 = g_adj_n[j],     e1 = g_adj_n[j + 1];
        int e2 = g_adj_n[j + 2], e3 = g_adj_n[j + 3];
        uint4 v0 = *(const uint4*)&g_S2h[(size_t)e0 * DIM + lane * 8];
        uint4 v1 = *(const uint4*)&g_S2h[(size_t)e1 * DIM + lane * 8];
        uint4 v2 = *(const uint4*)&g_S2h[(size_t)e2 * DIM + lane * 8];
        uint4 v3 = *(const uint4*)&g_S2h[(size_t)e3 * DIM + lane * 8];
        acc8(a, v0, 1.0f); acc8(a, v1, 1.0f); acc8(a, v2, 1.0f); acc8(a, v3, 1.0f);
    }
    for (; j < e; j++) {
        int e0 = g_adj_n[j];
        uint4 v0 = *(const uint4*)&g_S2h[(size_t)e0 * DIM + lane * 8];
        acc8(a, v0, 1.0f);
    }
    float dv = g_dv[w];
    float4 o0, o1;
    o0.x = a[0] * dv; o0.y = a[1] * dv; o0.z = a[2] * dv; o0.w = a[3] * dv;
    o1.x = a[4] * dv; o1.y = a[5] * dv; o1.z = a[6] * dv; o1.w = a[7] * dv;
    float* dst = out_g + (size_t)w * DIM + lane * 8;
    *(float4*)dst = o0;
    *(float4*)(dst + 4) = o1;
}

// ---------------- launch (fork/join: CSR chain || GEMM chain) ----------------
extern "C" void kernel_launch(void* const* d_in, const int* in_sizes, int n_in,
                              void* d_out, int out_size) {
    const float* X  = (const float*)d_in[0];
    const void*  ni = d_in[1];
    const void*  ei = d_in[2];
    const float* W  = (const float*)d_in[3];
    const float* b  = (const float*)d_in[4];
    float* out = (float*)d_out;

    static cudaStream_t sB = nullptr;
    static cudaEvent_t evRoot = nullptr, evB = nullptr;
    if (sB == nullptr) {
        cudaStreamCreateWithFlags(&sB, cudaStreamNonBlocking);
        cudaEventCreateWithFlags(&evRoot, cudaEventDisableTiming);
        cudaEventCreateWithFlags(&evB, cudaEventDisableTiming);
    }

    // fork: stream sB branches off the main (capture) stream
    cudaEventRecord(evRoot, 0);
    cudaStreamWaitEvent(sB, evRoot, 0);

    // ---- chain B (stream sB): W convert + GEMM (fused X conversion) ----
    convert_w_kernel<<<DIM, DIM, 0, sB>>>(W);
    dim3 ggrid(N_PAD / 128, DIM / 128);
    gemm_bf16_kernel<<<ggrid, 256, 0, sB>>>(X, b);

    // ---- chain A (main stream): CSR build ----
    detect_kernel<<<1, 1>>>(ni);
    zero_kernel<<<(N_NODES + 255) / 256, 256>>>();
    count_kernel<<<(NNZ + 255) / 256, 256>>>(ni, ei);
    scan_p1_kernel<<<dim3(CH_N, 2), 1024>>>();
    scan_p2_kernel<<<1, 128>>>();
    scan_p3_kernel<<<dim3(CH_N, 2), 1024>>>();
    fill_kernel<<<(NNZ + 255) / 256, 256>>>(ni, ei);

    // join: main stream waits for chain B
    cudaEventRecord(evB, sB);
    cudaStreamWaitEvent(0, evB, 0);

    edge_gather_kernel<<<(N_EDGES * 32 + 255) / 256, 256>>>();
    node_gather_kernel<<<(N_NODES * 32 + 255) / 256, 256>>>(out);
}

// round 10
// speedup vs baseline: 2.3143x; 1.0645x over previous
#include <cuda_runtime.h>
#include <cuda_bf16.h>
#include <cuda_fp16.h>
#include <cstdint>

#define N_NODES 50000
#define N_PAD   50048              // 391 * 128
#define N_EDGES 25000
#define NNZ     800000
#define DIM     256

#define CH_E ((N_EDGES + 1023) / 1024)   // 25
#define CH_N ((N_NODES + 1023) / 1024)   // 49

// ---------------- scratch ----------------------------------------------------
__device__ __align__(16) __half g_Zh [N_NODES * DIM];     // fp16(X@W + b)  25.6MB
__device__ __align__(16) __half g_S2h[N_EDGES * DIM];     // fp16 step2     12.8MB
__device__ __align__(16) __nv_bfloat16 g_Wthi[DIM * DIM]; // [n][k]
__device__ __align__(16) __nv_bfloat16 g_Wtlo[DIM * DIM]; // [n][k]
__device__ int   g_deg_v[N_NODES];
__device__ int   g_deg_e[N_EDGES];
__device__ float g_dv[N_NODES];
__device__ float g_de[N_EDGES];
__device__ int   g_off_e[N_EDGES + 1];
__device__ int   g_off_n[N_NODES + 1];
__device__ int   g_cur_e[N_EDGES];
__device__ int   g_cur_n[N_NODES];
__device__ int   g_adj_e[NNZ];
__device__ int   g_adj_n[NNZ];
__device__ int   g_part_e[32];
__device__ int   g_part_n[64];
__device__ int   g_is64;

// ---------------- helpers ----------------------------------------------------
__device__ __forceinline__ int idx_at(const void* p, int i, int is64) {
    if (is64) return (int)(((const long long*)p)[i]);
    return ((const int*)p)[i];
}
__device__ __forceinline__ void mma16816(float* c, const uint32_t* a, const uint32_t* b) {
    asm volatile(
        "mma.sync.aligned.m16n8k16.row.col.f32.bf16.bf16.f32 "
        "{%0,%1,%2,%3}, {%4,%5,%6,%7}, {%8,%9}, {%0,%1,%2,%3};\n"
        : "+f"(c[0]), "+f"(c[1]), "+f"(c[2]), "+f"(c[3])
        : "r"(a[0]), "r"(a[1]), "r"(a[2]), "r"(a[3]), "r"(b[0]), "r"(b[1]));
}
// accumulate 8 fp16 lanes (one uint4) into float acc[8], scaled by s
__device__ __forceinline__ void acc8(float* a, uint4 v, float s) {
    __half2 h0 = *(__half2*)&v.x, h1 = *(__half2*)&v.y;
    __half2 h2 = *(__half2*)&v.z, h3 = *(__half2*)&v.w;
    float2 f0 = __half22float2(h0), f1 = __half22float2(h1);
    float2 f2 = __half22float2(h2), f3 = __half22float2(h3);
    a[0] = fmaf(f0.x, s, a[0]); a[1] = fmaf(f0.y, s, a[1]);
    a[2] = fmaf(f1.x, s, a[2]); a[3] = fmaf(f1.y, s, a[3]);
    a[4] = fmaf(f2.x, s, a[4]); a[5] = fmaf(f2.y, s, a[5]);
    a[6] = fmaf(f3.x, s, a[6]); a[7] = fmaf(f3.y, s, a[7]);
}

// ---------------- detect index dtype (32 threads, 64 qwords) -----------------
__global__ void detect_kernel(const void* node_idx) {
    const unsigned long long* q = (const unsigned long long*)node_idx;
    int t = threadIdx.x;
    int bad = ((q[t] >> 32) != 0ull) || ((q[t + 32] >> 32) != 0ull);
    bad = __any_sync(0xffffffffu, bad);
    if (t == 0) g_is64 = bad ? 0 : 1;
}

// ---------------- zero counters (runs AFTER fill, overlapped with gathers) ---
__global__ void zero_kernel() {
    int i = blockIdx.x * blockDim.x + threadIdx.x;
    if (i < N_NODES) { g_deg_v[i] = 0; g_cur_n[i] = 0; }
    if (i < N_EDGES) { g_deg_e[i] = 0; g_cur_e[i] = 0; }
}

// ---------------- degree histogram -------------------------------------------
__global__ void count_kernel(const void* ni, const void* ei) {
    int i = blockIdx.x * blockDim.x + threadIdx.x;
    if (i >= NNZ) return;
    int is64 = g_is64;
    atomicAdd(&g_deg_v[idx_at(ni, i, is64)], 1);
    atomicAdd(&g_deg_e[idx_at(ei, i, is64)], 1);
}

// ---------------- convert W -> transposed bf16 hi/lo -------------------------
__global__ void convert_w_kernel(const float* __restrict__ W) {
    int n = blockIdx.x;
    int k = threadIdx.x;
    float w = W[(size_t)k * DIM + n];
    __nv_bfloat16 hi = __float2bfloat16_rn(w);
    __nv_bfloat16 lo = __float2bfloat16_rn(w - __bfloat162float(hi));
    g_Wthi[n * DIM + k] = hi;
    g_Wtlo[n * DIM + k] = lo;
}

// ---------------- GEMM (split bf16 tensor cores, A-register-prefetch) --------
// Zh = fp16(X @ W + b).  128x128 tile, K-chunks of 32, 8 warps (2m x 4n).
#define SA 40
__global__ __launch_bounds__(256, 2)
void gemm_bf16_kernel(const float* __restrict__ X,
                      const float* __restrict__ bias) {
    __shared__ __align__(16) __nv_bfloat16 As_hi[128][SA];
    __shared__ __align__(16) __nv_bfloat16 As_lo[128][SA];
    __shared__ __align__(16) __nv_bfloat16 Bs_hi[128][SA];
    __shared__ __align__(16) __nv_bfloat16 Bs_lo[128][SA];

    int t    = threadIdx.x;
    int warp = t >> 5, lane = t & 31;
    int wm = warp >> 2, wn = warp & 3;
    int g  = lane >> 2, q = lane & 3;
    int m0 = blockIdx.x * 128;
    int n0 = blockIdx.y * 128;

    float acc[4][4][4];
    #pragma unroll
    for (int i = 0; i < 4; i++)
        #pragma unroll
        for (int j = 0; j < 4; j++)
            #pragma unroll
            for (int r = 0; r < 4; r++) acc[i][j][r] = 0.0f;

    int lrow = t >> 1;
    int lseg = t & 1;
    int gr = m0 + lrow;

    // prefetch A chunk 0 into registers
    float vf[16];
    {
        if (gr < N_NODES) {
            const float4* src = (const float4*)&X[(size_t)gr * DIM + 0 + lseg * 16];
            float4 f0 = src[0], f1 = src[1], f2 = src[2], f3 = src[3];
            vf[0]=f0.x; vf[1]=f0.y; vf[2]=f0.z; vf[3]=f0.w;
            vf[4]=f1.x; vf[5]=f1.y; vf[6]=f1.z; vf[7]=f1.w;
            vf[8]=f2.x; vf[9]=f2.y; vf[10]=f2.z; vf[11]=f2.w;
            vf[12]=f3.x; vf[13]=f3.y; vf[14]=f3.z; vf[15]=f3.w;
        } else {
            #pragma unroll
            for (int k = 0; k < 16; k++) vf[k] = 0.0f;
        }
    }

    for (int k0 = 0; k0 < DIM; k0 += 32) {
        // convert prefetched A regs -> bf16 hi/lo smem
        {
            __nv_bfloat16 hi[16], lo[16];
            #pragma unroll
            for (int k = 0; k < 16; k++) {
                hi[k] = __float2bfloat16_rn(vf[k]);
                lo[k] = __float2bfloat16_rn(vf[k] - __bfloat162float(hi[k]));
            }
            *(uint4*)&As_hi[lrow][lseg * 16]     = ((uint4*)hi)[0];
            *(uint4*)&As_hi[lrow][lseg * 16 + 8] = ((uint4*)hi)[1];
            *(uint4*)&As_lo[lrow][lseg * 16]     = ((uint4*)lo)[0];
            *(uint4*)&As_lo[lrow][lseg * 16 + 8] = ((uint4*)lo)[1];
        }
        // B tile from L2-resident transposed bf16 W
        {
            const uint4* src = (const uint4*)&g_Wthi[(n0 + lrow) * DIM + k0 + lseg * 16];
            uint4 v0 = src[0], v1 = src[1];
            *(uint4*)&Bs_hi[lrow][lseg * 16]     = v0;
            *(uint4*)&Bs_hi[lrow][lseg * 16 + 8] = v1;
            const uint4* srl = (const uint4*)&g_Wtlo[(n0 + lrow) * DIM + k0 + lseg * 16];
            uint4 u0 = srl[0], u1 = srl[1];
            *(uint4*)&Bs_lo[lrow][lseg * 16]     = u0;
            *(uint4*)&Bs_lo[lrow][lseg * 16 + 8] = u1;
        }
        __syncthreads();

        // prefetch NEXT A chunk while MMAs run on this one
        if (k0 + 32 < DIM) {
            if (gr < N_NODES) {
                const float4* src = (const float4*)&X[(size_t)gr * DIM + k0 + 32 + lseg * 16];
                float4 f0 = src[0], f1 = src[1], f2 = src[2], f3 = src[3];
                vf[0]=f0.x; vf[1]=f0.y; vf[2]=f0.z; vf[3]=f0.w;
                vf[4]=f1.x; vf[5]=f1.y; vf[6]=f1.z; vf[7]=f1.w;
                vf[8]=f2.x; vf[9]=f2.y; vf[10]=f2.z; vf[11]=f2.w;
                vf[12]=f3.x; vf[13]=f3.y; vf[14]=f3.z; vf[15]=f3.w;
            }
        }

        #pragma unroll
        for (int ksub = 0; ksub < 32; ksub += 16) {
            uint32_t bh[4][2], bl[4][2];
            #pragma unroll
            for (int j = 0; j < 4; j++) {
                int nr = wn * 32 + j * 8 + g;
                int kc = ksub + q * 2;
                bh[j][0] = *(const uint32_t*)&Bs_hi[nr][kc];
                bh[j][1] = *(const uint32_t*)&Bs_hi[nr][kc + 8];
                bl[j][0] = *(const uint32_t*)&Bs_lo[nr][kc];
                bl[j][1] = *(const uint32_t*)&Bs_lo[nr][kc + 8];
            }
            #pragma unroll
            for (int i = 0; i < 4; i++) {
                int mr = wm * 64 + i * 16 + g;
                int kc = ksub + q * 2;
                uint32_t ah[4], al[4];
                ah[0] = *(const uint32_t*)&As_hi[mr][kc];
                ah[1] = *(const uint32_t*)&As_hi[mr + 8][kc];
                ah[2] = *(const uint32_t*)&As_hi[mr][kc + 8];
                ah[3] = *(const uint32_t*)&As_hi[mr + 8][kc + 8];
                al[0] = *(const uint32_t*)&As_lo[mr][kc];
                al[1] = *(const uint32_t*)&As_lo[mr + 8][kc];
                al[2] = *(const uint32_t*)&As_lo[mr][kc + 8];
                al[3] = *(const uint32_t*)&As_lo[mr + 8][kc + 8];
                #pragma unroll
                for (int j = 0; j < 4; j++) {
                    mma16816(acc[i][j], ah, bh[j]);
                    mma16816(acc[i][j], ah, bl[j]);
                    mma16816(acc[i][j], al, bh[j]);
                }
            }
        }
        __syncthreads();
    }

    // epilogue: + bias, store fp16 Zh
    #pragma unroll
    for (int j = 0; j < 4; j++) {
        int cb = n0 + wn * 32 + j * 8 + q * 2;
        float2 bb = *(const float2*)&bias[cb];
        #pragma unroll
        for (int i = 0; i < 4; i++) {
            int r = m0 + wm * 64 + i * 16 + g;
            if (r < N_NODES) {
                __half2 o = __floats2half2_rn(acc[i][j][0] + bb.x, acc[i][j][1] + bb.y);
                *(__half2*)&g_Zh[(size_t)r * DIM + cb] = o;
            }
            if (r + 8 < N_NODES) {
                __half2 o = __floats2half2_rn(acc[i][j][2] + bb.x, acc[i][j][3] + bb.y);
                *(__half2*)&g_Zh[(size_t)(r + 8) * DIM + cb] = o;
            }
        }
    }
}

// ---------------- scan phase 1 -----------------------------------------------
__global__ void scan_p1_kernel() {
    int which = blockIdx.y;
    int n          = which ? N_NODES : N_EDGES;
    const int* deg = which ? g_deg_v : g_deg_e;
    int*  off      = which ? g_off_n : g_off_e;
    float* dinv    = which ? g_dv    : g_de;
    int*  part     = which ? g_part_n : g_part_e;

    int base = blockIdx.x * 1024;
    if (base >= n) return;
    int tid = threadIdx.x;
    int i = base + tid;
    int v = (i < n) ? deg[i] : 0;

    int x = v;
    int lane = tid & 31, warp = tid >> 5;
    #pragma unroll
    for (int s = 1; s < 32; s <<= 1) {
        int t = __shfl_up_sync(0xffffffffu, x, s);
        if (lane >= s) x += t;
    }
    __shared__ int wsum[32];
    if (lane == 31) wsum[warp] = x;
    __syncthreads();
    if (warp == 0) {
        int y = wsum[lane];
        #pragma unroll
        for (int s = 1; s < 32; s <<= 1) {
            int t = __shfl_up_sync(0xffffffffu, y, s);
            if (lane >= s) y += t;
        }
        wsum[lane] = y;
    }
    __syncthreads();
    int incl = x + (warp ? wsum[warp - 1] : 0);
    if (i < n) {
        off[i] = incl - v;
        dinv[i] = (v > 0) ? (which ? rsqrtf((float)v) : 1.0f / (float)v) : 0.0f;
    }
    if (tid == 1023) part[blockIdx.x] = incl;
}

// ---------------- scan phase 2 -----------------------------------------------
__global__ void scan_p2_kernel() {
    __shared__ int pe[32], pn[64];
    int t = threadIdx.x;
    if (t < 32) pe[t] = (t < CH_E) ? g_part_e[t] : 0;
    if (t < 64) pn[t] = (t < CH_N) ? g_part_n[t] : 0;
    __syncthreads();
    #pragma unroll
    for (int s = 1; s < 64; s <<= 1) {
        int ve = (t < 32 && t >= s) ? pe[t - s] : 0;
        int vn = (t < 64 && t >= s) ? pn[t - s] : 0;
        __syncthreads();
        if (t < 32) pe[t] += ve;
        if (t < 64) pn[t] += vn;
        __syncthreads();
    }
    if (t < 32) g_part_e[t] = t ? pe[t - 1] : 0;
    if (t < 64) g_part_n[t] = t ? pn[t - 1] : 0;
    if (t == 0) { g_off_e[N_EDGES] = NNZ; g_off_n[N_NODES] = NNZ; }
}

// ---------------- scan phase 3 -----------------------------------------------
__global__ void scan_p3_kernel() {
    int which = blockIdx.y;
    int n    = which ? N_NODES : N_EDGES;
    int* off = which ? g_off_n : g_off_e;
    int i = blockIdx.x * 1024 + threadIdx.x;
    if (i < n) off[i] += (which ? g_part_n : g_part_e)[blockIdx.x];
}

// ---------------- CSR fill ----------------------------------------------------
__global__ void fill_kernel(const void* ni, const void* ei) {
    int i = blockIdx.x * blockDim.x + threadIdx.x;
    if (i >= NNZ) return;
    int is64 = g_is64;
    int n = idx_at(ni, i, is64);
    int e = idx_at(ei, i, is64);
    int pe = atomicAdd(&g_cur_e[e], 1);
    g_adj_e[g_off_e[e] + pe] = n;
    int pn = atomicAdd(&g_cur_n[n], 1);
    g_adj_n[g_off_n[n] + pn] = e;
}

// ---------------- S2h[e] = fp16( d_e * sum_{n in e} d_v[n] * Zh[n] ) ---------
// one warp per edge; lane owns 8 contiguous fp16 columns (one uint4 per row)
__global__ void edge_gather_kernel() {
    int w    = (blockIdx.x * blockDim.x + threadIdx.x) >> 5;
    int lane = threadIdx.x & 31;
    if (w >= N_EDGES) return;
    int s = g_off_e[w], e = g_off_e[w + 1];
    float a[8] = {0.f, 0.f, 0.f, 0.f, 0.f, 0.f, 0.f, 0.f};
    int j = s;
    int lim8 = s + ((e - s) & ~7);
    for (; j < lim8; j += 8) {
        int   n[8]; float d[8]; uint4 v[8];
        #pragma unroll
        for (int u = 0; u < 8; u++) n[u] = g_adj_e[j + u];
        #pragma unroll
        for (int u = 0; u < 8; u++) d[u] = g_dv[n[u]];
        #pragma unroll
        for (int u = 0; u < 8; u++)
            v[u] = *(const uint4*)&g_Zh[(size_t)n[u] * DIM + lane * 8];
        #pragma unroll
        for (int u = 0; u < 8; u++) acc8(a, v[u], d[u]);
    }
    for (; j < e; j++) {
        int n0 = g_adj_e[j];
        float d0 = g_dv[n0];
        uint4 v0 = *(const uint4*)&g_Zh[(size_t)n0 * DIM + lane * 8];
        acc8(a, v0, d0);
    }
    float de = g_de[w];
    __half2 o0 = __floats2half2_rn(a[0] * de, a[1] * de);
    __half2 o1 = __floats2half2_rn(a[2] * de, a[3] * de);
    __half2 o2 = __floats2half2_rn(a[4] * de, a[5] * de);
    __half2 o3 = __floats2half2_rn(a[6] * de, a[7] * de);
    uint4 st;
    st.x = *(uint32_t*)&o0; st.y = *(uint32_t*)&o1;
    st.z = *(uint32_t*)&o2; st.w = *(uint32_t*)&o3;
    *(uint4*)&g_S2h[(size_t)w * DIM + lane * 8] = st;
}

// ---------------- out[n] = d_v[n] * sum_{e of n} S2h[e]  (fp32 out) ----------
__global__ void node_gather_kernel(float* __restrict__ out_g) {
    int w    = (blockIdx.x * blockDim.x + threadIdx.x) >> 5;
    int lane = threadIdx.x & 31;
    if (w >= N_NODES) return;
    int s = g_off_n[w], e = g_off_n[w + 1];
    float a[8] = {0.f, 0.f, 0.f, 0.f, 0.f, 0.f, 0.f, 0.f};
    int j = s;
    int lim8 = s + ((e - s) & ~7);
    for (; j < lim8; j += 8) {
        int ee[8]; uint4 v[8];
        #pragma unroll
        for (int u = 0; u < 8; u++) ee[u] = g_adj_n[j + u];
        #pragma unroll
        for (int u = 0; u < 8; u++)
            v[u] = *(const uint4*)&g_S2h[(size_t)ee[u] * DIM + lane * 8];
        #pragma unroll
        for (int u = 0; u < 8; u++) acc8(a, v[u], 1.0f);
    }
    for (; j < e; j++) {
        int e0 = g_adj_n[j];
        uint4 v0 = *(const uint4*)&g_S2h[(size_t)e0 * DIM + lane * 8];
        acc8(a, v0, 1.0f);
    }
    float dv = g_dv[w];
    float4 o0, o1;
    o0.x = a[0] * dv; o0.y = a[1] * dv; o0.z = a[2] * dv; o0.w = a[3] * dv;
    o1.x = a[4] * dv; o1.y = a[5] * dv; o1.z = a[6] * dv; o1.w = a[7] * dv;
    float* dst = out_g + (size_t)w * DIM + lane * 8;
    *(float4*)dst = o0;
    *(float4*)(dst + 4) = o1;
}

// ---------------- launch (fork/join: CSR chain || GEMM chain) ----------------
extern "C" void kernel_launch(void* const* d_in, const int* in_sizes, int n_in,
                              void* d_out, int out_size) {
    const float* X  = (const float*)d_in[0];
    const void*  ni = d_in[1];
    const void*  ei = d_in[2];
    const float* W  = (const float*)d_in[3];
    const float* b  = (const float*)d_in[4];
    float* out = (float*)d_out;

    static cudaStream_t sB = nullptr;
    static cudaEvent_t evRoot = nullptr, evB = nullptr, evFill = nullptr, evZero = nullptr;
    if (sB == nullptr) {
        cudaStreamCreateWithFlags(&sB, cudaStreamNonBlocking);
        cudaEventCreateWithFlags(&evRoot, cudaEventDisableTiming);
        cudaEventCreateWithFlags(&evB, cudaEventDisableTiming);
        cudaEventCreateWithFlags(&evFill, cudaEventDisableTiming);
        cudaEventCreateWithFlags(&evZero, cudaEventDisableTiming);
    }

    // fork: stream sB branches off the main (capture) stream
    cudaEventRecord(evRoot, 0);
    cudaStreamWaitEvent(sB, evRoot, 0);

    // ---- chain B (stream sB): W convert + GEMM (fused X conversion) ----
    convert_w_kernel<<<DIM, DIM, 0, sB>>>(W);
    dim3 ggrid(N_PAD / 128, DIM / 128);
    gemm_bf16_kernel<<<ggrid, 256, 0, sB>>>(X, b);
    cudaEventRecord(evB, sB);

    // ---- chain A (main stream): CSR build (counters pre-zeroed invariant) ---
    detect_kernel<<<1, 32>>>(ni);
    count_kernel<<<(NNZ + 255) / 256, 256>>>(ni, ei);
    scan_p1_kernel<<<dim3(CH_N, 2), 1024>>>();
    scan_p2_kernel<<<1, 128>>>();
    scan_p3_kernel<<<dim3(CH_N, 2), 1024>>>();
    fill_kernel<<<(NNZ + 255) / 256, 256>>>(ni, ei);
    cudaEventRecord(evFill, 0);

    // re-zero counters for the NEXT run on sB, overlapped with edge_gather
    cudaStreamWaitEvent(sB, evFill, 0);
    zero_kernel<<<(N_NODES + 255) / 256, 256, 0, sB>>>();
    cudaEventRecord(evZero, sB);

    // join: main stream waits for chain B (GEMM) before gathers
    cudaStreamWaitEvent(0, evB, 0);

    edge_gather_kernel<<<(N_EDGES * 32 + 255) / 256, 256>>>();

    // join sB's tail (zero) back into the capture stream before the last node
    cudaStreamWaitEvent(0, evZero, 0);
    node_gather_kernel<<<(N_NODES * 32 + 255) / 256, 256>>>(out);
}

// round 11
// speedup vs baseline: 2.3429x; 1.0124x over previous
#include <cuda_runtime.h>
#include <cuda_bf16.h>
#include <cuda_fp16.h>
#include <cstdint>

#define N_NODES 50000
#define N_PAD   50048              // 391 * 128
#define N_EDGES 25000
#define NNZ     800000
#define DIM     256

#define CH_E ((N_EDGES + 1023) / 1024)   // 25
#define CH_N ((N_NODES + 1023) / 1024)   // 49

// ---------------- scratch ----------------------------------------------------
__device__ __align__(16) __half g_Zh [N_NODES * DIM];     // fp16(X@W + b)  25.6MB
__device__ __align__(16) __half g_S2h[N_EDGES * DIM];     // fp16 step2     12.8MB
__device__ __align__(16) float  g_Wt [DIM * DIM];         // tf32-rounded W^T [n][k]
__device__ int   g_deg_v[N_NODES];
__device__ int   g_deg_e[N_EDGES];
__device__ float g_dv[N_NODES];
__device__ float g_de[N_EDGES];
__device__ int   g_off_e[N_EDGES + 1];
__device__ int   g_off_n[N_NODES + 1];
__device__ int   g_cur_e[N_EDGES];
__device__ int   g_cur_n[N_NODES];
__device__ int   g_adj_e[NNZ];
__device__ int   g_adj_n[NNZ];
__device__ int   g_part_e[32];
__device__ int   g_part_n[64];
__device__ int   g_is64;

// ---------------- helpers ----------------------------------------------------
__device__ __forceinline__ int idx_at(const void* p, int i, int is64) {
    if (is64) return (int)(((const long long*)p)[i]);
    return ((const int*)p)[i];
}
__device__ __forceinline__ uint32_t f2tf32(float f) {
    uint32_t r;
    asm("cvt.rna.tf32.f32 %0, %1;" : "=r"(r) : "f"(f));
    return r;
}
__device__ __forceinline__ void mma_tf32(float* c, uint32_t a0, uint32_t a1,
                                         uint32_t a2, uint32_t a3,
                                         uint32_t b0, uint32_t b1) {
    asm volatile(
        "mma.sync.aligned.m16n8k8.row.col.f32.tf32.tf32.f32 "
        "{%0,%1,%2,%3}, {%4,%5,%6,%7}, {%8,%9}, {%0,%1,%2,%3};\n"
        : "+f"(c[0]), "+f"(c[1]), "+f"(c[2]), "+f"(c[3])
        : "r"(a0), "r"(a1), "r"(a2), "r"(a3), "r"(b0), "r"(b1));
}
// accumulate 8 fp16 lanes (one uint4) into float acc[8], scaled by s
__device__ __forceinline__ void acc8(float* a, uint4 v, float s) {
    __half2 h0 = *(__half2*)&v.x, h1 = *(__half2*)&v.y;
    __half2 h2 = *(__half2*)&v.z, h3 = *(__half2*)&v.w;
    float2 f0 = __half22float2(h0), f1 = __half22float2(h1);
    float2 f2 = __half22float2(h2), f3 = __half22float2(h3);
    a[0] = fmaf(f0.x, s, a[0]); a[1] = fmaf(f0.y, s, a[1]);
    a[2] = fmaf(f1.x, s, a[2]); a[3] = fmaf(f1.y, s, a[3]);
    a[4] = fmaf(f2.x, s, a[4]); a[5] = fmaf(f2.y, s, a[5]);
    a[6] = fmaf(f3.x, s, a[6]); a[7] = fmaf(f3.y, s, a[7]);
}

// ---------------- detect index dtype (32 threads, 64 qwords) -----------------
__global__ void detect_kernel(const void* node_idx) {
    const unsigned long long* q = (const unsigned long long*)node_idx;
    int t = threadIdx.x;
    int bad = ((q[t] >> 32) != 0ull) || ((q[t + 32] >> 32) != 0ull);
    bad = __any_sync(0xffffffffu, bad);
    if (t == 0) g_is64 = bad ? 0 : 1;
}

// ---------------- zero counters (runs AFTER fill, overlapped with gathers) ---
__global__ void zero_kernel() {
    int i = blockIdx.x * blockDim.x + threadIdx.x;
    if (i < N_NODES) { g_deg_v[i] = 0; g_cur_n[i] = 0; }
    if (i < N_EDGES) { g_deg_e[i] = 0; g_cur_e[i] = 0; }
}

// ---------------- degree histogram (4 nnz per thread) ------------------------
__global__ void count_kernel(const void* ni, const void* ei) {
    int base = (blockIdx.x * blockDim.x + threadIdx.x) * 4;
    if (base >= NNZ) return;
    int is64 = g_is64;
    int n[4], e[4];
    #pragma unroll
    for (int u = 0; u < 4; u++) n[u] = idx_at(ni, base + u, is64);
    #pragma unroll
    for (int u = 0; u < 4; u++) e[u] = idx_at(ei, base + u, is64);
    #pragma unroll
    for (int u = 0; u < 4; u++) {
        atomicAdd(&g_deg_v[n[u]], 1);
        atomicAdd(&g_deg_e[e[u]], 1);
    }
}

// ---------------- convert W -> transposed tf32-rounded fp32 ------------------
__global__ void convert_w_kernel(const float* __restrict__ W) {
    int n = blockIdx.x;
    int k = threadIdx.x;
    float w = W[(size_t)k * DIM + n];
    g_Wt[n * DIM + k] = __uint_as_float(f2tf32(w));
}

// ---------------- GEMM (single-pass tf32 tensor cores, A-reg prefetch) -------
// Zh = fp16(X @ W + b).  128x128 tile, K-chunks of 32, 8 warps (2m x 4n).
#define SAF 36
__global__ __launch_bounds__(256, 2)
void gemm_tf32_kernel(const float* __restrict__ X,
                      const float* __restrict__ bias) {
    __shared__ __align__(16) float As[128][SAF];
    __shared__ __align__(16) float Bs[128][SAF];

    int t    = threadIdx.x;
    int warp = t >> 5, lane = t & 31;
    int wm = warp >> 2, wn = warp & 3;
    int g  = lane >> 2, q = lane & 3;
    int m0 = blockIdx.x * 128;
    int n0 = blockIdx.y * 128;

    float acc[4][4][4];
    #pragma unroll
    for (int i = 0; i < 4; i++)
        #pragma unroll
        for (int j = 0; j < 4; j++)
            #pragma unroll
            for (int r = 0; r < 4; r++) acc[i][j][r] = 0.0f;

    int lrow = t >> 1;        // 0..127
    int lseg = t & 1;         // 16-float segment
    int gr = m0 + lrow;

    // prefetch A chunk 0 into registers
    float vf[16];
    {
        if (gr < N_NODES) {
            const float4* src = (const float4*)&X[(size_t)gr * DIM + 0 + lseg * 16];
            float4 f0 = src[0], f1 = src[1], f2 = src[2], f3 = src[3];
            vf[0]=f0.x; vf[1]=f0.y; vf[2]=f0.z; vf[3]=f0.w;
            vf[4]=f1.x; vf[5]=f1.y; vf[6]=f1.z; vf[7]=f1.w;
            vf[8]=f2.x; vf[9]=f2.y; vf[10]=f2.z; vf[11]=f2.w;
            vf[12]=f3.x; vf[13]=f3.y; vf[14]=f3.z; vf[15]=f3.w;
        } else {
            #pragma unroll
            for (int k = 0; k < 16; k++) vf[k] = 0.0f;
        }
    }

    for (int k0 = 0; k0 < DIM; k0 += 32) {
        // A: tf32-round prefetched regs -> smem (4x uint4 stores)
        {
            uint32_t tv[16];
            #pragma unroll
            for (int k = 0; k < 16; k++) tv[k] = f2tf32(vf[k]);
            #pragma unroll
            for (int p = 0; p < 4; p++)
                *(uint4*)&As[lrow][lseg * 16 + p * 4] = ((uint4*)tv)[p];
        }
        // B: copy from L2-resident pre-rounded g_Wt
        {
            const float4* src = (const float4*)&g_Wt[(n0 + lrow) * DIM + k0 + lseg * 16];
            #pragma unroll
            for (int p = 0; p < 4; p++)
                *(float4*)&Bs[lrow][lseg * 16 + p * 4] = src[p];
        }
        __syncthreads();

        // prefetch NEXT A chunk while MMAs run on this one
        if (k0 + 32 < DIM) {
            if (gr < N_NODES) {
                const float4* src = (const float4*)&X[(size_t)gr * DIM + k0 + 32 + lseg * 16];
                float4 f0 = src[0], f1 = src[1], f2 = src[2], f3 = src[3];
                vf[0]=f0.x; vf[1]=f0.y; vf[2]=f0.z; vf[3]=f0.w;
                vf[4]=f1.x; vf[5]=f1.y; vf[6]=f1.z; vf[7]=f1.w;
                vf[8]=f2.x; vf[9]=f2.y; vf[10]=f2.z; vf[11]=f2.w;
                vf[12]=f3.x; vf[13]=f3.y; vf[14]=f3.z; vf[15]=f3.w;
            }
        }

        #pragma unroll
        for (int ksub = 0; ksub < 32; ksub += 8) {
            uint32_t b0[4], b1[4];
            #pragma unroll
            for (int j = 0; j < 4; j++) {
                int nr = wn * 32 + j * 8 + g;
                b0[j] = *(const uint32_t*)&Bs[nr][ksub + q];
                b1[j] = *(const uint32_t*)&Bs[nr][ksub + q + 4];
            }
            #pragma unroll
            for (int i = 0; i < 4; i++) {
                int mr = wm * 64 + i * 16;
                uint32_t a0 = *(const uint32_t*)&As[mr + g][ksub + q];
                uint32_t a1 = *(const uint32_t*)&As[mr + 8 + g][ksub + q];
                uint32_t a2 = *(const uint32_t*)&As[mr + g][ksub + q + 4];
                uint32_t a3 = *(const uint32_t*)&As[mr + 8 + g][ksub + q + 4];
                #pragma unroll
                for (int j = 0; j < 4; j++)
                    mma_tf32(acc[i][j], a0, a1, a2, a3, b0[j], b1[j]);
            }
        }
        __syncthreads();
    }

    // epilogue: + bias, store fp16 Zh
    #pragma unroll
    for (int j = 0; j < 4; j++) {
        int cb = n0 + wn * 32 + j * 8 + q * 2;
        float2 bb = *(const float2*)&bias[cb];
        #pragma unroll
        for (int i = 0; i < 4; i++) {
            int r = m0 + wm * 64 + i * 16 + g;
            if (r < N_NODES) {
                __half2 o = __floats2half2_rn(acc[i][j][0] + bb.x, acc[i][j][1] + bb.y);
                *(__half2*)&g_Zh[(size_t)r * DIM + cb] = o;
            }
            if (r + 8 < N_NODES) {
                __half2 o = __floats2half2_rn(acc[i][j][2] + bb.x, acc[i][j][3] + bb.y);
                *(__half2*)&g_Zh[(size_t)(r + 8) * DIM + cb] = o;
            }
        }
    }
}

// ---------------- scan phase 1 -----------------------------------------------
__global__ void scan_p1_kernel() {
    int which = blockIdx.y;
    int n          = which ? N_NODES : N_EDGES;
    const int* deg = which ? g_deg_v : g_deg_e;
    int*  off      = which ? g_off_n : g_off_e;
    float* dinv    = which ? g_dv    : g_de;
    int*  part     = which ? g_part_n : g_part_e;

    int base = blockIdx.x * 1024;
    if (base >= n) return;
    int tid = threadIdx.x;
    int i = base + tid;
    int v = (i < n) ? deg[i] : 0;

    int x = v;
    int lane = tid & 31, warp = tid >> 5;
    #pragma unroll
    for (int s = 1; s < 32; s <<= 1) {
        int t = __shfl_up_sync(0xffffffffu, x, s);
        if (lane >= s) x += t;
    }
    __shared__ int wsum[32];
    if (lane == 31) wsum[warp] = x;
    __syncthreads();
    if (warp == 0) {
        int y = wsum[lane];
        #pragma unroll
        for (int s = 1; s < 32; s <<= 1) {
            int t = __shfl_up_sync(0xffffffffu, y, s);
            if (lane >= s) y += t;
        }
        wsum[lane] = y;
    }
    __syncthreads();
    int incl = x + (warp ? wsum[warp - 1] : 0);
    if (i < n) {
        off[i] = incl - v;
        dinv[i] = (v > 0) ? (which ? rsqrtf((float)v) : 1.0f / (float)v) : 0.0f;
    }
    if (tid == 1023) part[blockIdx.x] = incl;
}

// ---------------- scan phase 2 -----------------------------------------------
__global__ void scan_p2_kernel() {
    __shared__ int pe[32], pn[64];
    int t = threadIdx.x;
    if (t < 32) pe[t] = (t < CH_E) ? g_part_e[t] : 0;
    if (t < 64) pn[t] = (t < CH_N) ? g_part_n[t] : 0;
    __syncthreads();
    #pragma unroll
    for (int s = 1; s < 64; s <<= 1) {
        int ve = (t < 32 && t >= s) ? pe[t - s] : 0;
        int vn = (t < 64 && t >= s) ? pn[t - s] : 0;
        __syncthreads();
        if (t < 32) pe[t] += ve;
        if (t < 64) pn[t] += vn;
        __syncthreads();
    }
    if (t < 32) g_part_e[t] = t ? pe[t - 1] : 0;
    if (t < 64) g_part_n[t] = t ? pn[t - 1] : 0;
    if (t == 0) { g_off_e[N_EDGES] = NNZ; g_off_n[N_NODES] = NNZ; }
}

// ---------------- scan phase 3 -----------------------------------------------
__global__ void scan_p3_kernel() {
    int which = blockIdx.y;
    int n    = which ? N_NODES : N_EDGES;
    int* off = which ? g_off_n : g_off_e;
    int i = blockIdx.x * 1024 + threadIdx.x;
    if (i < n) off[i] += (which ? g_part_n : g_part_e)[blockIdx.x];
}

// ---------------- CSR fill (4 nnz per thread) --------------------------------
__global__ void fill_kernel(const void* ni, const void* ei) {
    int base = (blockIdx.x * blockDim.x + threadIdx.x) * 4;
    if (base >= NNZ) return;
    int is64 = g_is64;
    int n[4], e[4];
    #pragma unroll
    for (int u = 0; u < 4; u++) n[u] = idx_at(ni, base + u, is64);
    #pragma unroll
    for (int u = 0; u < 4; u++) e[u] = idx_at(ei, base + u, is64);
    #pragma unroll
    for (int u = 0; u < 4; u++) {
        int pe = atomicAdd(&g_cur_e[e[u]], 1);
        g_adj_e[g_off_e[e[u]] + pe] = n[u];
    }
    #pragma unroll
    for (int u = 0; u < 4; u++) {
        int pn = atomicAdd(&g_cur_n[n[u]], 1);
        g_adj_n[g_off_n[n[u]] + pn] = e[u];
    }
}

// ---------------- S2h[e] = fp16( d_e * sum_{n in e} d_v[n] * Zh[n] ) ---------
__global__ void edge_gather_kernel() {
    int w    = (blockIdx.x * blockDim.x + threadIdx.x) >> 5;
    int lane = threadIdx.x & 31;
    if (w >= N_EDGES) return;
    int s = g_off_e[w], e = g_off_e[w + 1];
    float a[8] = {0.f, 0.f, 0.f, 0.f, 0.f, 0.f, 0.f, 0.f};
    int j = s;
    int lim8 = s + ((e - s) & ~7);
    for (; j < lim8; j += 8) {
        int   n[8]; float d[8]; uint4 v[8];
        #pragma unroll
        for (int u = 0; u < 8; u++) n[u] = g_adj_e[j + u];
        #pragma unroll
        for (int u = 0; u < 8; u++) d[u] = g_dv[n[u]];
        #pragma unroll
        for (int u = 0; u < 8; u++)
            v[u] = *(const uint4*)&g_Zh[(size_t)n[u] * DIM + lane * 8];
        #pragma unroll
        for (int u = 0; u < 8; u++) acc8(a, v[u], d[u]);
    }
    for (; j < e; j++) {
        int n0 = g_adj_e[j];
        float d0 = g_dv[n0];
        uint4 v0 = *(const uint4*)&g_Zh[(size_t)n0 * DIM + lane * 8];
        acc8(a, v0, d0);
    }
    float de = g_de[w];
    __half2 o0 = __floats2half2_rn(a[0] * de, a[1] * de);
    __half2 o1 = __floats2half2_rn(a[2] * de, a[3] * de);
    __half2 o2 = __floats2half2_rn(a[4] * de, a[5] * de);
    __half2 o3 = __floats2half2_rn(a[6] * de, a[7] * de);
    uint4 st;
    st.x = *(uint32_t*)&o0; st.y = *(uint32_t*)&o1;
    st.z = *(uint32_t*)&o2; st.w = *(uint32_t*)&o3;
    *(uint4*)&g_S2h[(size_t)w * DIM + lane * 8] = st;
}

// ---------------- out[n] = d_v[n] * sum_{e of n} S2h[e]  (fp32 out) ----------
__global__ void node_gather_kernel(float* __restrict__ out_g) {
    int w    = (blockIdx.x * blockDim.x + threadIdx.x) >> 5;
    int lane = threadIdx.x & 31;
    if (w >= N_NODES) return;
    int s = g_off_n[w], e = g_off_n[w + 1];
    float a[8] = {0.f, 0.f, 0.f, 0.f, 0.f, 0.f, 0.f, 0.f};
    int j = s;
    int lim8 = s + ((e - s) & ~7);
    for (; j < lim8; j += 8) {
        int ee[8]; uint4 v[8];
        #pragma unroll
        for (int u = 0; u < 8; u++) ee[u] = g_adj_n[j + u];
        #pragma unroll
        for (int u = 0; u < 8; u++)
            v[u] = *(const uint4*)&g_S2h[(size_t)ee[u] * DIM + lane * 8];
        #pragma unroll
        for (int u = 0; u < 8; u++) acc8(a, v[u], 1.0f);
    }
    for (; j < e; j++) {
        int e0 = g_adj_n[j];
        uint4 v0 = *(const uint4*)&g_S2h[(size_t)e0 * DIM + lane * 8];
        acc8(a, v0, 1.0f);
    }
    float dv = g_dv[w];
    float4 o0, o1;
    o0.x = a[0] * dv; o0.y = a[1] * dv; o0.z = a[2] * dv; o0.w = a[3] * dv;
    o1.x = a[4] * dv; o1.y = a[5] * dv; o1.z = a[6] * dv; o1.w = a[7] * dv;
    float* dst = out_g + (size_t)w * DIM + lane * 8;
    *(float4*)dst = o0;
    *(float4*)(dst + 4) = o1;
}

// ---------------- launch (fork/join: CSR chain || GEMM chain) ----------------
extern "C" void kernel_launch(void* const* d_in, const int* in_sizes, int n_in,
                              void* d_out, int out_size) {
    const float* X  = (const float*)d_in[0];
    const void*  ni = d_in[1];
    const void*  ei = d_in[2];
    const float* W  = (const float*)d_in[3];
    const float* b  = (const float*)d_in[4];
    float* out = (float*)d_out;

    static cudaStream_t sB = nullptr;
    static cudaEvent_t evRoot = nullptr, evB = nullptr, evFill = nullptr, evZero = nullptr;
    if (sB == nullptr) {
        cudaStreamCreateWithFlags(&sB, cudaStreamNonBlocking);
        cudaEventCreateWithFlags(&evRoot, cudaEventDisableTiming);
        cudaEventCreateWithFlags(&evB, cudaEventDisableTiming);
        cudaEventCreateWithFlags(&evFill, cudaEventDisableTiming);
        cudaEventCreateWithFlags(&evZero, cudaEventDisableTiming);
    }

    // fork: stream sB branches off the main (capture) stream
    cudaEventRecord(evRoot, 0);
    cudaStreamWaitEvent(sB, evRoot, 0);

    // ---- chain B (stream sB): W transpose/round + tf32 GEMM ----
    convert_w_kernel<<<DIM, DIM, 0, sB>>>(W);
    dim3 ggrid(N_PAD / 128, DIM / 128);
    gemm_tf32_kernel<<<ggrid, 256, 0, sB>>>(X, b);
    cudaEventRecord(evB, sB);

    // ---- chain A (main stream): CSR build (counters pre-zeroed invariant) ---
    detect_kernel<<<1, 32>>>(ni);
    count_kernel<<<(NNZ / 4 + 255) / 256, 256>>>(ni, ei);
    scan_p1_kernel<<<dim3(CH_N, 2), 1024>>>();
    scan_p2_kernel<<<1, 128>>>();
    scan_p3_kernel<<<dim3(CH_N, 2), 1024>>>();
    fill_kernel<<<(NNZ / 4 + 255) / 256, 256>>>(ni, ei);
    cudaEventRecord(evFill, 0);

    // re-zero counters for the NEXT run on sB, overlapped with edge_gather
    cudaStreamWaitEvent(sB, evFill, 0);
    zero_kernel<<<(N_NODES + 255) / 256, 256, 0, sB>>>();
    cudaEventRecord(evZero, sB);

    // join: main stream waits for chain B (GEMM) before gathers
    cudaStreamWaitEvent(0, evB, 0);

    edge_gather_kernel<<<(N_EDGES * 32 + 255) / 256, 256>>>();

    // join sB's tail (zero) back into the capture stream before the last node
    cudaStreamWaitEvent(0, evZero, 0);
    node_gather_kernel<<<(N_NODES * 32 + 255) / 256, 256>>>(out);
}

// round 12
// speedup vs baseline: 2.4423x; 1.0424x over previous
#include <cuda_runtime.h>
#include <cuda_bf16.h>
#include <cuda_fp16.h>
#include <cstdint>

#define N_NODES 50000
#define N_PAD   50048              // 391 * 128
#define N_EDGES 25000
#define NNZ     800000
#define DIM     256

#define CH_E ((N_EDGES + 1023) / 1024)   // 25
#define CH_N ((N_NODES + 1023) / 1024)   // 49

// ---------------- scratch ----------------------------------------------------
__device__ __align__(16) __half g_Zh [N_NODES * DIM];     // fp16(X@W + b)  25.6MB
__device__ __align__(16) __half g_S2h[N_EDGES * DIM];     // fp16 step2     12.8MB
__device__ __align__(16) float  g_Wt [DIM * DIM];         // tf32-rounded W^T [n][k]
__device__ int   g_deg_v[N_NODES];
__device__ int   g_deg_e[N_EDGES];
__device__ float g_dv[N_NODES];
__device__ float g_de[N_EDGES];
__device__ int   g_off_e[N_EDGES + 1];
__device__ int   g_off_n[N_NODES + 1];
__device__ int   g_rank_v[NNZ];           // rank of nnz i within its node segment
__device__ int   g_rank_e[NNZ];           // rank of nnz i within its edge segment
__device__ int   g_adj_e[NNZ];
__device__ int   g_adj_n[NNZ];
__device__ int   g_part_e[32];
__device__ int   g_part_n[64];
__device__ int   g_is64;

// ---------------- helpers ----------------------------------------------------
__device__ __forceinline__ int idx_at(const void* p, int i, int is64) {
    if (is64) return (int)(((const long long*)p)[i]);
    return ((const int*)p)[i];
}
__device__ __forceinline__ uint32_t f2tf32(float f) {
    uint32_t r;
    asm("cvt.rna.tf32.f32 %0, %1;" : "=r"(r) : "f"(f));
    return r;
}
__device__ __forceinline__ void mma_tf32(float* c, uint32_t a0, uint32_t a1,
                                         uint32_t a2, uint32_t a3,
                                         uint32_t b0, uint32_t b1) {
    asm volatile(
        "mma.sync.aligned.m16n8k8.row.col.f32.tf32.tf32.f32 "
        "{%0,%1,%2,%3}, {%4,%5,%6,%7}, {%8,%9}, {%0,%1,%2,%3};\n"
        : "+f"(c[0]), "+f"(c[1]), "+f"(c[2]), "+f"(c[3])
        : "r"(a0), "r"(a1), "r"(a2), "r"(a3), "r"(b0), "r"(b1));
}
// accumulate 8 fp16 lanes (one uint4) into float acc[8], scaled by s
__device__ __forceinline__ void acc8(float* a, uint4 v, float s) {
    __half2 h0 = *(__half2*)&v.x, h1 = *(__half2*)&v.y;
    __half2 h2 = *(__half2*)&v.z, h3 = *(__half2*)&v.w;
    float2 f0 = __half22float2(h0), f1 = __half22float2(h1);
    float2 f2 = __half22float2(h2), f3 = __half22float2(h3);
    a[0] = fmaf(f0.x, s, a[0]); a[1] = fmaf(f0.y, s, a[1]);
    a[2] = fmaf(f1.x, s, a[2]); a[3] = fmaf(f1.y, s, a[3]);
    a[4] = fmaf(f2.x, s, a[4]); a[5] = fmaf(f2.y, s, a[5]);
    a[6] = fmaf(f3.x, s, a[6]); a[7] = fmaf(f3.y, s, a[7]);
}

// ---------------- detect index dtype (32 threads, 64 qwords) -----------------
__global__ void detect_kernel(const void* node_idx) {
    const unsigned long long* q = (const unsigned long long*)node_idx;
    int t = threadIdx.x;
    int bad = ((q[t] >> 32) != 0ull) || ((q[t + 32] >> 32) != 0ull);
    bad = __any_sync(0xffffffffu, bad);
    if (t == 0) g_is64 = bad ? 0 : 1;
}

// ---------------- zero degree counters (off critical path) -------------------
__global__ void zero_kernel() {
    int i = blockIdx.x * blockDim.x + threadIdx.x;
    if (i < N_NODES) g_deg_v[i] = 0;
    if (i < N_EDGES) g_deg_e[i] = 0;
}

// ---------------- degree histogram + per-nnz rank capture --------------------
__global__ void count_kernel(const void* ni, const void* ei) {
    int base = (blockIdx.x * blockDim.x + threadIdx.x) * 4;
    if (base >= NNZ) return;
    int is64 = g_is64;
    int n[4], e[4];
    #pragma unroll
    for (int u = 0; u < 4; u++) n[u] = idx_at(ni, base + u, is64);
    #pragma unroll
    for (int u = 0; u < 4; u++) e[u] = idx_at(ei, base + u, is64);
    #pragma unroll
    for (int u = 0; u < 4; u++)
        g_rank_v[base + u] = atomicAdd(&g_deg_v[n[u]], 1);
    #pragma unroll
    for (int u = 0; u < 4; u++)
        g_rank_e[base + u] = atomicAdd(&g_deg_e[e[u]], 1);
}

// ---------------- convert W -> transposed tf32-rounded fp32 ------------------
__global__ void convert_w_kernel(const float* __restrict__ W) {
    int n = blockIdx.x;
    int k = threadIdx.x;
    float w = W[(size_t)k * DIM + n];
    g_Wt[n * DIM + k] = __uint_as_float(f2tf32(w));
}

// ---------------- GEMM (single-pass tf32 tensor cores, A-reg prefetch) -------
// Zh = fp16(X @ W + b).  128x128 tile, K-chunks of 32, 8 warps (2m x 4n).
#define SAF 36
__global__ __launch_bounds__(256, 2)
void gemm_tf32_kernel(const float* __restrict__ X,
                      const float* __restrict__ bias) {
    __shared__ __align__(16) float As[128][SAF];
    __shared__ __align__(16) float Bs[128][SAF];

    int t    = threadIdx.x;
    int warp = t >> 5, lane = t & 31;
    int wm = warp >> 2, wn = warp & 3;
    int g  = lane >> 2, q = lane & 3;
    int m0 = blockIdx.x * 128;
    int n0 = blockIdx.y * 128;

    float acc[4][4][4];
    #pragma unroll
    for (int i = 0; i < 4; i++)
        #pragma unroll
        for (int j = 0; j < 4; j++)
            #pragma unroll
            for (int r = 0; r < 4; r++) acc[i][j][r] = 0.0f;

    int lrow = t >> 1;        // 0..127
    int lseg = t & 1;         // 16-float segment
    int gr = m0 + lrow;

    // prefetch A chunk 0 into registers
    float vf[16];
    {
        if (gr < N_NODES) {
            const float4* src = (const float4*)&X[(size_t)gr * DIM + 0 + lseg * 16];
            float4 f0 = src[0], f1 = src[1], f2 = src[2], f3 = src[3];
            vf[0]=f0.x; vf[1]=f0.y; vf[2]=f0.z; vf[3]=f0.w;
            vf[4]=f1.x; vf[5]=f1.y; vf[6]=f1.z; vf[7]=f1.w;
            vf[8]=f2.x; vf[9]=f2.y; vf[10]=f2.z; vf[11]=f2.w;
            vf[12]=f3.x; vf[13]=f3.y; vf[14]=f3.z; vf[15]=f3.w;
        } else {
            #pragma unroll
            for (int k = 0; k < 16; k++) vf[k] = 0.0f;
        }
    }

    for (int k0 = 0; k0 < DIM; k0 += 32) {
        // A: tf32-round prefetched regs -> smem
        {
            uint32_t tv[16];
            #pragma unroll
            for (int k = 0; k < 16; k++) tv[k] = f2tf32(vf[k]);
            #pragma unroll
            for (int p = 0; p < 4; p++)
                *(uint4*)&As[lrow][lseg * 16 + p * 4] = ((uint4*)tv)[p];
        }
        // B: copy from L2-resident pre-rounded g_Wt
        {
            const float4* src = (const float4*)&g_Wt[(n0 + lrow) * DIM + k0 + lseg * 16];
            #pragma unroll
            for (int p = 0; p < 4; p++)
                *(float4*)&Bs[lrow][lseg * 16 + p * 4] = src[p];
        }
        __syncthreads();

        // prefetch NEXT A chunk while MMAs run on this one
        if (k0 + 32 < DIM) {
            if (gr < N_NODES) {
                const float4* src = (const float4*)&X[(size_t)gr * DIM + k0 + 32 + lseg * 16];
                float4 f0 = src[0], f1 = src[1], f2 = src[2], f3 = src[3];
                vf[0]=f0.x; vf[1]=f0.y; vf[2]=f0.z; vf[3]=f0.w;
                vf[4]=f1.x; vf[5]=f1.y; vf[6]=f1.z; vf[7]=f1.w;
                vf[8]=f2.x; vf[9]=f2.y; vf[10]=f2.z; vf[11]=f2.w;
                vf[12]=f3.x; vf[13]=f3.y; vf[14]=f3.z; vf[15]=f3.w;
            }
        }

        #pragma unroll
        for (int ksub = 0; ksub < 32; ksub += 8) {
            uint32_t b0[4], b1[4];
            #pragma unroll
            for (int j = 0; j < 4; j++) {
                int nr = wn * 32 + j * 8 + g;
                b0[j] = *(const uint32_t*)&Bs[nr][ksub + q];
                b1[j] = *(const uint32_t*)&Bs[nr][ksub + q + 4];
            }
            #pragma unroll
            for (int i = 0; i < 4; i++) {
                int mr = wm * 64 + i * 16;
                uint32_t a0 = *(const uint32_t*)&As[mr + g][ksub + q];
                uint32_t a1 = *(const uint32_t*)&As[mr + 8 + g][ksub + q];
                uint32_t a2 = *(const uint32_t*)&As[mr + g][ksub + q + 4];
                uint32_t a3 = *(const uint32_t*)&As[mr + 8 + g][ksub + q + 4];
                #pragma unroll
                for (int j = 0; j < 4; j++)
                    mma_tf32(acc[i][j], a0, a1, a2, a3, b0[j], b1[j]);
            }
        }
        __syncthreads();
    }

    // epilogue: + bias, store fp16 Zh
    #pragma unroll
    for (int j = 0; j < 4; j++) {
        int cb = n0 + wn * 32 + j * 8 + q * 2;
        float2 bb = *(const float2*)&bias[cb];
        #pragma unroll
        for (int i = 0; i < 4; i++) {
            int r = m0 + wm * 64 + i * 16 + g;
            if (r < N_NODES) {
                __half2 o = __floats2half2_rn(acc[i][j][0] + bb.x, acc[i][j][1] + bb.y);
                *(__half2*)&g_Zh[(size_t)r * DIM + cb] = o;
            }
            if (r + 8 < N_NODES) {
                __half2 o = __floats2half2_rn(acc[i][j][2] + bb.x, acc[i][j][3] + bb.y);
                *(__half2*)&g_Zh[(size_t)(r + 8) * DIM + cb] = o;
            }
        }
    }
}

// ---------------- scan phase 1 -----------------------------------------------
__global__ void scan_p1_kernel() {
    int which = blockIdx.y;
    int n          = which ? N_NODES : N_EDGES;
    const int* deg = which ? g_deg_v : g_deg_e;
    int*  off      = which ? g_off_n : g_off_e;
    float* dinv    = which ? g_dv    : g_de;
    int*  part     = which ? g_part_n : g_part_e;

    int base = blockIdx.x * 1024;
    if (base >= n) return;
    int tid = threadIdx.x;
    int i = base + tid;
    int v = (i < n) ? deg[i] : 0;

    int x = v;
    int lane = tid & 31, warp = tid >> 5;
    #pragma unroll
    for (int s = 1; s < 32; s <<= 1) {
        int t = __shfl_up_sync(0xffffffffu, x, s);
        if (lane >= s) x += t;
    }
    __shared__ int wsum[32];
    if (lane == 31) wsum[warp] = x;
    __syncthreads();
    if (warp == 0) {
        int y = wsum[lane];
        #pragma unroll
        for (int s = 1; s < 32; s <<= 1) {
            int t = __shfl_up_sync(0xffffffffu, y, s);
            if (lane >= s) y += t;
        }
        wsum[lane] = y;
    }
    __syncthreads();
    int incl = x + (warp ? wsum[warp - 1] : 0);
    if (i < n) {
        off[i] = incl - v;
        dinv[i] = (v > 0) ? (which ? rsqrtf((float)v) : 1.0f / (float)v) : 0.0f;
    }
    if (tid == 1023) part[blockIdx.x] = incl;
}

// ---------------- scan phase 2 -----------------------------------------------
__global__ void scan_p2_kernel() {
    __shared__ int pe[32], pn[64];
    int t = threadIdx.x;
    if (t < 32) pe[t] = (t < CH_E) ? g_part_e[t] : 0;
    if (t < 64) pn[t] = (t < CH_N) ? g_part_n[t] : 0;
    __syncthreads();
    #pragma unroll
    for (int s = 1; s < 64; s <<= 1) {
        int ve = (t < 32 && t >= s) ? pe[t - s] : 0;
        int vn = (t < 64 && t >= s) ? pn[t - s] : 0;
        __syncthreads();
        if (t < 32) pe[t] += ve;
        if (t < 64) pn[t] += vn;
        __syncthreads();
    }
    if (t < 32) g_part_e[t] = t ? pe[t - 1] : 0;
    if (t < 64) g_part_n[t] = t ? pn[t - 1] : 0;
    if (t == 0) { g_off_e[N_EDGES] = NNZ; g_off_n[N_NODES] = NNZ; }
}

// ---------------- scan phase 3 -----------------------------------------------
__global__ void scan_p3_kernel() {
    int which = blockIdx.y;
    int n    = which ? N_NODES : N_EDGES;
    int* off = which ? g_off_n : g_off_e;
    int i = blockIdx.x * 1024 + threadIdx.x;
    if (i < n) off[i] += (which ? g_part_n : g_part_e)[blockIdx.x];
}

// ---------------- CSR fill, edge side (atomic-free via ranks) ----------------
__global__ void fill_e_kernel(const void* ni, const void* ei) {
    int base = (blockIdx.x * blockDim.x + threadIdx.x) * 4;
    if (base >= NNZ) return;
    int is64 = g_is64;
    int n[4], e[4], r[4];
    #pragma unroll
    for (int u = 0; u < 4; u++) n[u] = idx_at(ni, base + u, is64);
    #pragma unroll
    for (int u = 0; u < 4; u++) e[u] = idx_at(ei, base + u, is64);
    #pragma unroll
    for (int u = 0; u < 4; u++) r[u] = g_rank_e[base + u];
    #pragma unroll
    for (int u = 0; u < 4; u++)
        g_adj_e[g_off_e[e[u]] + r[u]] = n[u];
}

// ---------------- CSR fill, node side (atomic-free via ranks) ----------------
__global__ void fill_n_kernel(const void* ni, const void* ei) {
    int base = (blockIdx.x * blockDim.x + threadIdx.x) * 4;
    if (base >= NNZ) return;
    int is64 = g_is64;
    int n[4], e[4], r[4];
    #pragma unroll
    for (int u = 0; u < 4; u++) n[u] = idx_at(ni, base + u, is64);
    #pragma unroll
    for (int u = 0; u < 4; u++) e[u] = idx_at(ei, base + u, is64);
    #pragma unroll
    for (int u = 0; u < 4; u++) r[u] = g_rank_v[base + u];
    #pragma unroll
    for (int u = 0; u < 4; u++)
        g_adj_n[g_off_n[n[u]] + r[u]] = e[u];
}

// ---------------- S2h[e] = fp16( d_e * sum_{n in e} d_v[n] * Zh[n] ) ---------
__global__ void edge_gather_kernel() {
    int w    = (blockIdx.x * blockDim.x + threadIdx.x) >> 5;
    int lane = threadIdx.x & 31;
    if (w >= N_EDGES) return;
    int s = g_off_e[w], e = g_off_e[w + 1];
    float a[8] = {0.f, 0.f, 0.f, 0.f, 0.f, 0.f, 0.f, 0.f};
    int j = s;
    int lim8 = s + ((e - s) & ~7);
    for (; j < lim8; j += 8) {
        int   n[8]; float d[8]; uint4 v[8];
        #pragma unroll
        for (int u = 0; u < 8; u++) n[u] = g_adj_e[j + u];
        #pragma unroll
        for (int u = 0; u < 8; u++) d[u] = g_dv[n[u]];
        #pragma unroll
        for (int u = 0; u < 8; u++)
            v[u] = *(const uint4*)&g_Zh[(size_t)n[u] * DIM + lane * 8];
        #pragma unroll
        for (int u = 0; u < 8; u++) acc8(a, v[u], d[u]);
    }
    for (; j < e; j++) {
        int n0 = g_adj_e[j];
        float d0 = g_dv[n0];
        uint4 v0 = *(const uint4*)&g_Zh[(size_t)n0 * DIM + lane * 8];
        acc8(a, v0, d0);
    }
    float de = g_de[w];
    __half2 o0 = __floats2half2_rn(a[0] * de, a[1] * de);
    __half2 o1 = __floats2half2_rn(a[2] * de, a[3] * de);
    __half2 o2 = __floats2half2_rn(a[4] * de, a[5] * de);
    __half2 o3 = __floats2half2_rn(a[6] * de, a[7] * de);
    uint4 st;
    st.x = *(uint32_t*)&o0; st.y = *(uint32_t*)&o1;
    st.z = *(uint32_t*)&o2; st.w = *(uint32_t*)&o3;
    *(uint4*)&g_S2h[(size_t)w * DIM + lane * 8] = st;
}

// ---------------- out[n] = d_v[n] * sum_{e of n} S2h[e]  (fp32 out) ----------
__global__ void node_gather_kernel(float* __restrict__ out_g) {
    int w    = (blockIdx.x * blockDim.x + threadIdx.x) >> 5;
    int lane = threadIdx.x & 31;
    if (w >= N_NODES) return;
    int s = g_off_n[w], e = g_off_n[w + 1];
    float a[8] = {0.f, 0.f, 0.f, 0.f, 0.f, 0.f, 0.f, 0.f};
    int j = s;
    int lim8 = s + ((e - s) & ~7);
    for (; j < lim8; j += 8) {
        int ee[8]; uint4 v[8];
        #pragma unroll
        for (int u = 0; u < 8; u++) ee[u] = g_adj_n[j + u];
        #pragma unroll
        for (int u = 0; u < 8; u++)
            v[u] = *(const uint4*)&g_S2h[(size_t)ee[u] * DIM + lane * 8];
        #pragma unroll
        for (int u = 0; u < 8; u++) acc8(a, v[u], 1.0f);
    }
    for (; j < e; j++) {
        int e0 = g_adj_n[j];
        uint4 v0 = *(const uint4*)&g_S2h[(size_t)e0 * DIM + lane * 8];
        acc8(a, v0, 1.0f);
    }
    float dv = g_dv[w];
    float4 o0, o1;
    o0.x = a[0] * dv; o0.y = a[1] * dv; o0.z = a[2] * dv; o0.w = a[3] * dv;
    o1.x = a[4] * dv; o1.y = a[5] * dv; o1.z = a[6] * dv; o1.w = a[7] * dv;
    float* dst = out_g + (size_t)w * DIM + lane * 8;
    *(float4*)dst = o0;
    *(float4*)(dst + 4) = o1;
}

// ---------------- launch (3-way fork/join DAG) -------------------------------
extern "C" void kernel_launch(void* const* d_in, const int* in_sizes, int n_in,
                              void* d_out, int out_size) {
    const float* X  = (const float*)d_in[0];
    const void*  ni = d_in[1];
    const void*  ei = d_in[2];
    const float* W  = (const float*)d_in[3];
    const float* b  = (const float*)d_in[4];
    float* out = (float*)d_out;

    static cudaStream_t sB = nullptr, sC = nullptr;
    static cudaEvent_t evRoot = nullptr, evB = nullptr, evScan = nullptr, evC = nullptr;
    if (sB == nullptr) {
        cudaStreamCreateWithFlags(&sB, cudaStreamNonBlocking);
        cudaStreamCreateWithFlags(&sC, cudaStreamNonBlocking);
        cudaEventCreateWithFlags(&evRoot, cudaEventDisableTiming);
        cudaEventCreateWithFlags(&evB, cudaEventDisableTiming);
        cudaEventCreateWithFlags(&evScan, cudaEventDisableTiming);
        cudaEventCreateWithFlags(&evC, cudaEventDisableTiming);
    }

    // fork: sB branches off the main (capture) stream at the root
    cudaEventRecord(evRoot, 0);
    cudaStreamWaitEvent(sB, evRoot, 0);

    // ---- chain B (sB): W transpose/round + tf32 GEMM ----
    convert_w_kernel<<<DIM, DIM, 0, sB>>>(W);
    dim3 ggrid(N_PAD / 128, DIM / 128);
    gemm_tf32_kernel<<<ggrid, 256, 0, sB>>>(X, b);
    cudaEventRecord(evB, sB);

    // ---- chain A (main): detect -> count(+ranks) -> scans ----
    detect_kernel<<<1, 32>>>(ni);
    count_kernel<<<(NNZ / 4 + 255) / 256, 256>>>(ni, ei);
    scan_p1_kernel<<<dim3(CH_N, 2), 1024>>>();
    scan_p2_kernel<<<1, 128>>>();
    scan_p3_kernel<<<dim3(CH_N, 2), 1024>>>();
    cudaEventRecord(evScan, 0);

    // ---- chain C (sC): node-side fill + counter re-zero, overlapped ----
    cudaStreamWaitEvent(sC, evScan, 0);
    fill_n_kernel<<<(NNZ / 4 + 255) / 256, 256, 0, sC>>>(ni, ei);
    zero_kernel<<<(N_NODES + 255) / 256, 256, 0, sC>>>();
    cudaEventRecord(evC, sC);

    // ---- chain A continues: edge-side fill (atomic-free) ----
    fill_e_kernel<<<(NNZ / 4 + 255) / 256, 256>>>(ni, ei);

    // join GEMM, then edge gather
    cudaStreamWaitEvent(0, evB, 0);
    edge_gather_kernel<<<(N_EDGES * 32 + 255) / 256, 256>>>();

    // join chain C, then node gather
    cudaStreamWaitEvent(0, evC, 0);
    node_gather_kernel<<<(N_NODES * 32 + 255) / 256, 256>>>(out);
}